// round 6
// baseline (speedup 1.0000x reference)
#include <cuda_runtime.h>

#define HH 16
#define LLEN 512
#define DD 1024
#define BB 4
#define BHN (BB*HH)      // 64
#define MR (BB*LLEN)     // 2048

// ---------------- scratch (no cudaMalloc allowed) ----------------
__device__ float g_qh[BHN * LLEN * 64];   // [b*H+h][l][64], Q pre-scaled by 1/8
__device__ float g_kh[BHN * LLEN * 64];
__device__ float g_vh[BHN * LLEN * 64];
__device__ float g_ctx[MR * DD];          // attention output, [b,l,h*64+dv]
__device__ float g_pre[MR * DD];          // pre-LayerNorm

// ---------------- shared GEMM core: C[128x128] tile, K=1024 ----------------
// 256 threads, 8x8 per thread, BK=8, As stored transposed.
__device__ __forceinline__ void gemm_core(const float* __restrict__ A,
                                          const float* __restrict__ W,
                                          float (&acc)[8][8])
{
    __shared__ float As[8 * 128];
    __shared__ float Bs[8 * 128];
    const int tid = threadIdx.x;
    const int m0 = blockIdx.y * 128;
    const int n0 = blockIdx.x * 128;
    const int tr = tid >> 4, tc = tid & 15;
    const int a_row = tid >> 1, a_off = (tid & 1) * 4;
    const int b_row = tid >> 5, b_col = (tid & 31) * 4;

    for (int k0 = 0; k0 < DD; k0 += 8) {
        float4 av = *(const float4*)&A[(size_t)(m0 + a_row) * DD + k0 + a_off];
        float4 bv = *(const float4*)&W[(size_t)(k0 + b_row) * DD + n0 + b_col];
        __syncthreads();
        As[(a_off + 0) * 128 + a_row] = av.x;
        As[(a_off + 1) * 128 + a_row] = av.y;
        As[(a_off + 2) * 128 + a_row] = av.z;
        As[(a_off + 3) * 128 + a_row] = av.w;
        *(float4*)&Bs[b_row * 128 + b_col] = bv;
        __syncthreads();
#pragma unroll
        for (int kk = 0; kk < 8; kk++) {
            float ra[8], rb[8];
            *(float4*)&ra[0] = *(const float4*)&As[kk * 128 + tr * 8];
            *(float4*)&ra[4] = *(const float4*)&As[kk * 128 + tr * 8 + 4];
            *(float4*)&rb[0] = *(const float4*)&Bs[kk * 128 + tc * 8];
            *(float4*)&rb[4] = *(const float4*)&Bs[kk * 128 + tc * 8 + 4];
#pragma unroll
            for (int i = 0; i < 8; i++)
#pragma unroll
                for (int j = 0; j < 8; j++)
                    acc[i][j] = fmaf(ra[i], rb[j], acc[i][j]);
        }
    }
}

// ---------------- QKV projection: grid (8, 16, 3) ----------------
__global__ __launch_bounds__(256, 2)
void proj_kernel(const float* __restrict__ q, const float* __restrict__ k,
                 const float* __restrict__ v,
                 const float* __restrict__ wq, const float* __restrict__ wk,
                 const float* __restrict__ wv,
                 const float* __restrict__ bq, const float* __restrict__ bk,
                 const float* __restrict__ bv)
{
    const int z = blockIdx.z;
    const float* A    = (z == 0) ? q  : (z == 1) ? k  : v;
    const float* W    = (z == 0) ? wq : (z == 1) ? wk : wv;
    const float* bias = (z == 0) ? bq : (z == 1) ? bk : bv;
    float* out        = (z == 0) ? g_qh : (z == 1) ? g_kh : g_vh;
    const float scale = (z == 0) ? 0.125f : 1.0f;   // fold 1/sqrt(64) into Q

    float acc[8][8];
#pragma unroll
    for (int i = 0; i < 8; i++)
#pragma unroll
        for (int j = 0; j < 8; j++) acc[i][j] = 0.f;

    gemm_core(A, W, acc);

    const int tid = threadIdx.x;
    const int tr = tid >> 4, tc = tid & 15;
    const int m0 = blockIdx.y * 128, n0 = blockIdx.x * 128;
#pragma unroll
    for (int i = 0; i < 8; i++) {
        const int m = m0 + tr * 8 + i;
        const int b = m >> 9, l = m & 511;
#pragma unroll
        for (int j = 0; j < 8; j++) {
            const int n = n0 + tc * 8 + j;
            const int h = n >> 6, d = n & 63;
            out[(size_t)(((b << 4) + h) * LLEN + l) * 64 + d] =
                (acc[i][j] + bias[n]) * scale;
        }
    }
}

// ---------------- output projection + bias + residual: grid (8, 16) ----------------
__global__ __launch_bounds__(256, 2)
void outproj_kernel(const float* __restrict__ wo, const float* __restrict__ bo,
                    const float* __restrict__ resid)
{
    float acc[8][8];
#pragma unroll
    for (int i = 0; i < 8; i++)
#pragma unroll
        for (int j = 0; j < 8; j++) acc[i][j] = 0.f;

    gemm_core(g_ctx, wo, acc);

    const int tid = threadIdx.x;
    const int tr = tid >> 4, tc = tid & 15;
    const int m0 = blockIdx.y * 128, n0 = blockIdx.x * 128;
#pragma unroll
    for (int i = 0; i < 8; i++) {
        const int m = m0 + tr * 8 + i;
#pragma unroll
        for (int j = 0; j < 8; j++) {
            const int n = n0 + tc * 8 + j;
            g_pre[(size_t)m * DD + n] = acc[i][j] + bo[n] + resid[(size_t)m * DD + n];
        }
    }
}

// ---------------- attention: grid (4, 64), 256 threads, 132 KB dyn smem ----------------
// Per block: 128 queries of one (b,h); loop over 4 key blocks of 128 keys.
#define ATTN_SMEM_FLOATS (64*128 + 8*128 + 128*64 + 128*128)
__global__ __launch_bounds__(256, 1)
void attn_kernel(const float* __restrict__ bias, const float* __restrict__ gbias)
{
    extern __shared__ float sm[];
    float* Qs = sm;                  // [64 d][128 q]  transposed
    float* Ks = Qs + 64 * 128;       // [8 d][128 key] chunk, transposed
    float* Vs = Ks + 8 * 128;        // [128 key][64 dv]
    float* Ps = Vs + 128 * 64;       // [128 q][128 key]

    const int tid = threadIdx.x;
    const int bh  = blockIdx.y;          // b*16 + h
    const int q0  = blockIdx.x * 128;
    const int tr  = tid >> 4, tc = tid & 15;

    const float* qptr  = g_qh + (size_t)(bh * LLEN + q0) * 64;
    const float* kbase = g_kh + (size_t)bh * LLEN * 64;
    const float* vbase = g_vh + (size_t)bh * LLEN * 64;
    const float* bptr  = bias  + (size_t)(bh * LLEN + q0) * LLEN;
    const float* gptr  = gbias + (size_t)(bh * LLEN + q0) * LLEN;

    // stage Q transposed (chunked so the transpose store is only 2-way conflicted)
    {
        const int row = tid >> 1;
        const int dq  = (tid & 1) * 4;
#pragma unroll
        for (int c = 0; c < 8; c++) {
            float4 v4 = *(const float4*)&qptr[row * 64 + c * 8 + dq];
            Qs[(c * 8 + dq + 0) * 128 + row] = v4.x;
            Qs[(c * 8 + dq + 1) * 128 + row] = v4.y;
            Qs[(c * 8 + dq + 2) * 128 + row] = v4.z;
            Qs[(c * 8 + dq + 3) * 128 + row] = v4.w;
        }
    }

    float m_run[8], l_run[8], o[8][4];
#pragma unroll
    for (int i = 0; i < 8; i++) {
        m_run[i] = -1e30f; l_run[i] = 0.f;
        o[i][0] = o[i][1] = o[i][2] = o[i][3] = 0.f;
    }

    for (int kb = 0; kb < 4; kb++) {
        const int k0 = kb * 128;
        // stage V (natural layout) — protected vs previous PV by end-of-loop sync
#pragma unroll
        for (int rep = 0; rep < 8; rep++) {
            int idx = rep * 256 + tid;
            int row = idx >> 4;
            int dv  = (idx & 15) * 4;
            *(float4*)&Vs[row * 64 + dv] =
                *(const float4*)&vbase[(size_t)(k0 + row) * 64 + dv];
        }

        float s[8][8];
#pragma unroll
        for (int i = 0; i < 8; i++)
#pragma unroll
            for (int j = 0; j < 8; j++) s[i][j] = 0.f;

        const int krow = tid >> 1;
        const int kd   = (tid & 1) * 4;
        for (int c = 0; c < 8; c++) {           // 8 d-chunks of 8
            float4 kv = *(const float4*)&kbase[(size_t)(k0 + krow) * 64 + c * 8 + kd];
            __syncthreads();                     // prev chunk compute done
            Ks[(kd + 0) * 128 + krow] = kv.x;
            Ks[(kd + 1) * 128 + krow] = kv.y;
            Ks[(kd + 2) * 128 + krow] = kv.z;
            Ks[(kd + 3) * 128 + krow] = kv.w;
            __syncthreads();
#pragma unroll
            for (int kk = 0; kk < 8; kk++) {
                float ra[8], rb[8];
                *(float4*)&ra[0] = *(const float4*)&Qs[(c * 8 + kk) * 128 + tr * 8];
                *(float4*)&ra[4] = *(const float4*)&Qs[(c * 8 + kk) * 128 + tr * 8 + 4];
                *(float4*)&rb[0] = *(const float4*)&Ks[kk * 128 + tc * 8];
                *(float4*)&rb[4] = *(const float4*)&Ks[kk * 128 + tc * 8 + 4];
#pragma unroll
                for (int i = 0; i < 8; i++)
#pragma unroll
                    for (int j = 0; j < 8; j++)
                        s[i][j] = fmaf(ra[i], rb[j], s[i][j]);
            }
        }

        // add mask bias + structural bias (coalesced float4 streams)
#pragma unroll
        for (int i = 0; i < 8; i++) {
            const float* br = bptr + (size_t)(tr * 8 + i) * LLEN + k0 + tc * 8;
            const float* gr = gptr + (size_t)(tr * 8 + i) * LLEN + k0 + tc * 8;
            float4 b0 = *(const float4*)br, b1 = *(const float4*)(br + 4);
            float4 g0 = *(const float4*)gr, g1 = *(const float4*)(gr + 4);
            s[i][0] += b0.x + g0.x; s[i][1] += b0.y + g0.y;
            s[i][2] += b0.z + g0.z; s[i][3] += b0.w + g0.w;
            s[i][4] += b1.x + g1.x; s[i][5] += b1.y + g1.y;
            s[i][6] += b1.z + g1.z; s[i][7] += b1.w + g1.w;
        }

        // online softmax (row stats shared across the 16 tx lanes)
#pragma unroll
        for (int i = 0; i < 8; i++) {
            float tm = s[i][0];
#pragma unroll
            for (int j = 1; j < 8; j++) tm = fmaxf(tm, s[i][j]);
#pragma unroll
            for (int off = 8; off > 0; off >>= 1)
                tm = fmaxf(tm, __shfl_xor_sync(0xffffffffu, tm, off));
            const float mn  = fmaxf(m_run[i], tm);
            const float fac = __expf(m_run[i] - mn);
            m_run[i] = mn;
            float ls = 0.f;
#pragma unroll
            for (int j = 0; j < 8; j++) {
                float p = __expf(s[i][j] - mn);
                s[i][j] = p;
                ls += p;
            }
            l_run[i] = l_run[i] * fac + ls;
            o[i][0] *= fac; o[i][1] *= fac; o[i][2] *= fac; o[i][3] *= fac;
        }

        // stage P
#pragma unroll
        for (int i = 0; i < 8; i++) {
            *(float4*)&Ps[(tr * 8 + i) * 128 + tc * 8] =
                make_float4(s[i][0], s[i][1], s[i][2], s[i][3]);
            *(float4*)&Ps[(tr * 8 + i) * 128 + tc * 8 + 4] =
                make_float4(s[i][4], s[i][5], s[i][6], s[i][7]);
        }
        __syncthreads();

        // O += P * V
#pragma unroll 4
        for (int c = 0; c < 128; c++) {
            float4 rv = *(const float4*)&Vs[c * 64 + tc * 4];
#pragma unroll
            for (int i = 0; i < 8; i++) {
                float p = Ps[(tr * 8 + i) * 128 + c];
                o[i][0] = fmaf(p, rv.x, o[i][0]);
                o[i][1] = fmaf(p, rv.y, o[i][1]);
                o[i][2] = fmaf(p, rv.z, o[i][2]);
                o[i][3] = fmaf(p, rv.w, o[i][3]);
            }
        }
        __syncthreads();
    }

    // finalize: combine partial row sums across tx lanes, normalize, write ctx
    const int b = bh >> 4, h = bh & 15;
#pragma unroll
    for (int i = 0; i < 8; i++) {
        float lt = l_run[i];
#pragma unroll
        for (int off = 8; off > 0; off >>= 1)
            lt += __shfl_xor_sync(0xffffffffu, lt, off);
        const float inv = 1.0f / lt;
        const int qrow = q0 + tr * 8 + i;
        float4 ov = make_float4(o[i][0] * inv, o[i][1] * inv,
                                o[i][2] * inv, o[i][3] * inv);
        *(float4*)&g_ctx[(size_t)(b * LLEN + qrow) * DD + h * 64 + tc * 4] = ov;
    }
}

// ---------------- LayerNorm: grid 2048, 256 threads ----------------
__global__ __launch_bounds__(256)
void ln_kernel(const float* __restrict__ gamma, const float* __restrict__ beta,
               float* __restrict__ out)
{
    __shared__ float red[8];
    const int row = blockIdx.x, tid = threadIdx.x;
    const float4 xv = *(const float4*)&g_pre[(size_t)row * DD + tid * 4];

    float sv = xv.x + xv.y + xv.z + xv.w;
#pragma unroll
    for (int off = 16; off > 0; off >>= 1) sv += __shfl_xor_sync(0xffffffffu, sv, off);
    if ((tid & 31) == 0) red[tid >> 5] = sv;
    __syncthreads();
    float tot = 0.f;
#pragma unroll
    for (int w = 0; w < 8; w++) tot += red[w];
    const float mean = tot * (1.0f / 1024.0f);

    const float dx = xv.x - mean, dy = xv.y - mean, dz = xv.z - mean, dw = xv.w - mean;
    float ss = dx * dx + dy * dy + dz * dz + dw * dw;
    __syncthreads();
#pragma unroll
    for (int off = 16; off > 0; off >>= 1) ss += __shfl_xor_sync(0xffffffffu, ss, off);
    if ((tid & 31) == 0) red[tid >> 5] = ss;
    __syncthreads();
    float tot2 = 0.f;
#pragma unroll
    for (int w = 0; w < 8; w++) tot2 += red[w];
    const float rstd = rsqrtf(tot2 * (1.0f / 1024.0f) + 1e-6f);

    const float4 gv = *(const float4*)&gamma[tid * 4];
    const float4 bv = *(const float4*)&beta[tid * 4];
    float4 ov;
    ov.x = dx * rstd * gv.x + bv.x;
    ov.y = dy * rstd * gv.y + bv.y;
    ov.z = dz * rstd * gv.z + bv.z;
    ov.w = dw * rstd * gv.w + bv.w;
    *(float4*)&out[(size_t)row * DD + tid * 4] = ov;
}

// ---------------- launch ----------------
extern "C" void kernel_launch(void* const* d_in, const int* in_sizes, int n_in,
                              void* d_out, int out_size)
{
    const float* q     = (const float*)d_in[0];
    const float* k     = (const float*)d_in[1];
    const float* v     = (const float*)d_in[2];
    const float* bias  = (const float*)d_in[3];
    const float* gbias = (const float*)d_in[4];
    const float* wq    = (const float*)d_in[5];
    const float* bq    = (const float*)d_in[6];
    const float* wk    = (const float*)d_in[7];
    const float* bk    = (const float*)d_in[8];
    const float* wv    = (const float*)d_in[9];
    const float* bv    = (const float*)d_in[10];
    const float* wo    = (const float*)d_in[11];
    const float* bo    = (const float*)d_in[12];
    const float* ln_g  = (const float*)d_in[13];
    const float* ln_b  = (const float*)d_in[14];
    float* out = (float*)d_out;

    const int attn_smem = ATTN_SMEM_FLOATS * (int)sizeof(float);   // 135168 B
    cudaFuncSetAttribute(attn_kernel,
                         cudaFuncAttributeMaxDynamicSharedMemorySize, attn_smem);

    proj_kernel<<<dim3(8, 16, 3), 256>>>(q, k, v, wq, wk, wv, bq, bk, bv);
    attn_kernel<<<dim3(4, 64), 256, attn_smem>>>(bias, gbias);
    outproj_kernel<<<dim3(8, 16), 256>>>(wo, bo, q);
    ln_kernel<<<2048, 256>>>(ln_g, ln_b, out);
}

// round 7
// speedup vs baseline: 1.6042x; 1.6042x over previous
#include <cuda_runtime.h>

#define HH 16
#define LLEN 512
#define DD 1024
#define BB 4
#define BHN (BB*HH)      // 64
#define MR (BB*LLEN)     // 2048
#define SA 132           // smem row stride (128 + 4 pad)

// ---------------- scratch (no cudaMalloc allowed) ----------------
__device__ float g_qh[BHN * LLEN * 64];   // [b*H+h][l][64], Q pre-scaled by 1/8
__device__ float g_kh[BHN * LLEN * 64];
__device__ float g_vh[BHN * LLEN * 64];
__device__ float g_ctx[MR * DD];          // attention output, [b,l,h*64+dv]
__device__ float g_pre[MR * DD];          // pre-LayerNorm

// ---------------- tf32 helpers ----------------
__device__ __forceinline__ unsigned f2tf32(float f) {
    unsigned r;
    asm("cvt.rna.tf32.f32 %0, %1;" : "=r"(r) : "f"(f));
    return r;
}

__device__ __forceinline__ void mma_tf32(float (&c)[4], const unsigned (&a)[4],
                                         const unsigned (&b)[2]) {
    asm("mma.sync.aligned.m16n8k8.row.col.f32.tf32.tf32.f32 "
        "{%0,%1,%2,%3}, {%4,%5,%6,%7}, {%8,%9}, {%0,%1,%2,%3};"
        : "+f"(c[0]), "+f"(c[1]), "+f"(c[2]), "+f"(c[3])
        : "r"(a[0]), "r"(a[1]), "r"(a[2]), "r"(a[3]), "r"(b[0]), "r"(b[1]));
}

// ---------------- TF32 mma GEMM core ----------------
// C[128x128] tile of C[2048 x 1024] = A[2048 x 1024(K)] * W[1024(K) x 1024].
// 256 threads = 8 warps; warp tile 64x32 (warp grid 2m x 4n); K-tile 32.
// acc[mt][nt][4] are the m16n8 fragments.
__device__ __forceinline__ void mma_core(const float* __restrict__ A,
                                         const float* __restrict__ W,
                                         float (&acc)[4][4][4])
{
    __shared__ unsigned As[32 * SA];   // [k][m], tf32 bits
    __shared__ unsigned Ws[32 * SA];   // [k][n], tf32 bits

    const int tid  = threadIdx.x;
    const int w    = tid >> 5, lane = tid & 31;
    const int g    = lane >> 2, t = lane & 3;
    const int wm   = (w & 1) * 64, wn = (w >> 1) * 32;
    const int m0   = blockIdx.y * 128, n0 = blockIdx.x * 128;

    const int ar  = tid >> 1,  akq = (tid & 1) * 16;   // A: row, k-quarter
    const int wkr = tid >> 3,  wnq = (tid & 7) * 16;   // W: k-row, n-chunk

    for (int k0 = 0; k0 < DD; k0 += 32) {
        float4 av[4], wv[4];
#pragma unroll
        for (int i = 0; i < 4; i++)
            av[i] = *(const float4*)&A[(size_t)(m0 + ar) * DD + k0 + akq + i * 4];
#pragma unroll
        for (int i = 0; i < 4; i++)
            wv[i] = *(const float4*)&W[(size_t)(k0 + wkr) * DD + n0 + wnq + i * 4];

        __syncthreads();   // previous tile's compute done
#pragma unroll
        for (int i = 0; i < 4; i++) {
            const float* p = (const float*)&av[i];
#pragma unroll
            for (int jj = 0; jj < 4; jj++)
                As[(akq + i * 4 + jj) * SA + ar] = f2tf32(p[jj]);
        }
#pragma unroll
        for (int i = 0; i < 4; i++) {
            const float* p = (const float*)&wv[i];
#pragma unroll
            for (int jj = 0; jj < 4; jj++)
                Ws[wkr * SA + wnq + i * 4 + jj] = f2tf32(p[jj]);
        }
        __syncthreads();

#pragma unroll
        for (int ks = 0; ks < 4; ks++) {
            const int kk = ks * 8;
            unsigned a[4][4], b[4][2];
#pragma unroll
            for (int mt = 0; mt < 4; mt++) {
                const int m = wm + mt * 16 + g;
                a[mt][0] = As[(kk + t) * SA + m];
                a[mt][1] = As[(kk + t) * SA + m + 8];
                a[mt][2] = As[(kk + t + 4) * SA + m];
                a[mt][3] = As[(kk + t + 4) * SA + m + 8];
            }
#pragma unroll
            for (int nt = 0; nt < 4; nt++) {
                const int n = wn + nt * 8 + g;
                b[nt][0] = Ws[(kk + t) * SA + n];
                b[nt][1] = Ws[(kk + t + 4) * SA + n];
            }
#pragma unroll
            for (int mt = 0; mt < 4; mt++)
#pragma unroll
                for (int nt = 0; nt < 4; nt++)
                    mma_tf32(acc[mt][nt], a[mt], b[nt]);
        }
    }
}

// ---------------- QKV projection: grid (8, 16, 3) ----------------
__global__ __launch_bounds__(256, 2)
void proj_kernel(const float* __restrict__ q, const float* __restrict__ k,
                 const float* __restrict__ v,
                 const float* __restrict__ wq, const float* __restrict__ wk,
                 const float* __restrict__ wv,
                 const float* __restrict__ bq, const float* __restrict__ bk,
                 const float* __restrict__ bv)
{
    const int z = blockIdx.z;
    const float* A    = (z == 0) ? q  : (z == 1) ? k  : v;
    const float* W    = (z == 0) ? wq : (z == 1) ? wk : wv;
    const float* bias = (z == 0) ? bq : (z == 1) ? bk : bv;
    float* out        = (z == 0) ? g_qh : (z == 1) ? g_kh : g_vh;
    const float scale = (z == 0) ? 0.125f : 1.0f;   // fold 1/sqrt(64) into Q

    float acc[4][4][4];
#pragma unroll
    for (int mt = 0; mt < 4; mt++)
#pragma unroll
        for (int nt = 0; nt < 4; nt++)
#pragma unroll
            for (int i = 0; i < 4; i++) acc[mt][nt][i] = 0.f;

    mma_core(A, W, acc);

    const int tid = threadIdx.x;
    const int w = tid >> 5, lane = tid & 31;
    const int g = lane >> 2, t = lane & 3;
    const int wm = (w & 1) * 64, wn = (w >> 1) * 32;
    const int m0 = blockIdx.y * 128, n0 = blockIdx.x * 128;

#pragma unroll
    for (int mt = 0; mt < 4; mt++) {
        const int r0 = m0 + wm + mt * 16 + g;
#pragma unroll
        for (int nt = 0; nt < 4; nt++) {
            const int c0 = n0 + wn + nt * 8 + 2 * t;
#pragma unroll
            for (int e = 0; e < 4; e++) {
                const int r = r0 + (e >> 1) * 8;        // e=0,1 -> r0 ; e=2,3 -> r0+8
                const int c = c0 + (e & 1);
                const int b = r >> 9, l = r & 511;
                const int h = c >> 6, d = c & 63;
                out[(size_t)(((b << 4) + h) * LLEN + l) * 64 + d] =
                    (acc[mt][nt][e] + bias[c]) * scale;
            }
        }
    }
}

// ---------------- output projection + bias + residual: grid (8, 16) ----------------
__global__ __launch_bounds__(256, 2)
void outproj_kernel(const float* __restrict__ wo, const float* __restrict__ bo,
                    const float* __restrict__ resid)
{
    float acc[4][4][4];
#pragma unroll
    for (int mt = 0; mt < 4; mt++)
#pragma unroll
        for (int nt = 0; nt < 4; nt++)
#pragma unroll
            for (int i = 0; i < 4; i++) acc[mt][nt][i] = 0.f;

    mma_core(g_ctx, wo, acc);

    const int tid = threadIdx.x;
    const int w = tid >> 5, lane = tid & 31;
    const int g = lane >> 2, t = lane & 3;
    const int wm = (w & 1) * 64, wn = (w >> 1) * 32;
    const int m0 = blockIdx.y * 128, n0 = blockIdx.x * 128;

#pragma unroll
    for (int mt = 0; mt < 4; mt++) {
        const int r0 = m0 + wm + mt * 16 + g;
#pragma unroll
        for (int nt = 0; nt < 4; nt++) {
            const int c0 = n0 + wn + nt * 8 + 2 * t;
#pragma unroll
            for (int e = 0; e < 4; e++) {
                const int r = r0 + (e >> 1) * 8;
                const int c = c0 + (e & 1);
                g_pre[(size_t)r * DD + c] =
                    acc[mt][nt][e] + bo[c] + resid[(size_t)r * DD + c];
            }
        }
    }
}

// ---------------- attention: grid (4, 64), 256 threads, 132 KB dyn smem ----------------
#define ATTN_SMEM_FLOATS (64*128 + 8*128 + 128*64 + 128*128)
__global__ __launch_bounds__(256, 1)
void attn_kernel(const float* __restrict__ bias, const float* __restrict__ gbias)
{
    extern __shared__ float sm[];
    float* Qs = sm;                  // [64 d][128 q]  transposed
    float* Ks = Qs + 64 * 128;       // [8 d][128 key] chunk, transposed
    float* Vs = Ks + 8 * 128;        // [128 key][64 dv]
    float* Ps = Vs + 128 * 64;       // [128 q][128 key]

    const int tid = threadIdx.x;
    const int bh  = blockIdx.y;          // b*16 + h
    const int q0  = blockIdx.x * 128;
    const int tr  = tid >> 4, tc = tid & 15;

    const float* qptr  = g_qh + (size_t)(bh * LLEN + q0) * 64;
    const float* kbase = g_kh + (size_t)bh * LLEN * 64;
    const float* vbase = g_vh + (size_t)bh * LLEN * 64;
    const float* bptr  = bias  + (size_t)(bh * LLEN + q0) * LLEN;
    const float* gptr  = gbias + (size_t)(bh * LLEN + q0) * LLEN;

    {
        const int row = tid >> 1;
        const int dq  = (tid & 1) * 4;
#pragma unroll
        for (int c = 0; c < 8; c++) {
            float4 v4 = *(const float4*)&qptr[row * 64 + c * 8 + dq];
            Qs[(c * 8 + dq + 0) * 128 + row] = v4.x;
            Qs[(c * 8 + dq + 1) * 128 + row] = v4.y;
            Qs[(c * 8 + dq + 2) * 128 + row] = v4.z;
            Qs[(c * 8 + dq + 3) * 128 + row] = v4.w;
        }
    }

    float m_run[8], l_run[8], o[8][4];
#pragma unroll
    for (int i = 0; i < 8; i++) {
        m_run[i] = -1e30f; l_run[i] = 0.f;
        o[i][0] = o[i][1] = o[i][2] = o[i][3] = 0.f;
    }

    for (int kb = 0; kb < 4; kb++) {
        const int k0 = kb * 128;
#pragma unroll
        for (int rep = 0; rep < 8; rep++) {
            int idx = rep * 256 + tid;
            int row = idx >> 4;
            int dv  = (idx & 15) * 4;
            *(float4*)&Vs[row * 64 + dv] =
                *(const float4*)&vbase[(size_t)(k0 + row) * 64 + dv];
        }

        float s[8][8];
#pragma unroll
        for (int i = 0; i < 8; i++)
#pragma unroll
            for (int j = 0; j < 8; j++) s[i][j] = 0.f;

        const int krow = tid >> 1;
        const int kd   = (tid & 1) * 4;
        for (int c = 0; c < 8; c++) {
            float4 kv = *(const float4*)&kbase[(size_t)(k0 + krow) * 64 + c * 8 + kd];
            __syncthreads();
            Ks[(kd + 0) * 128 + krow] = kv.x;
            Ks[(kd + 1) * 128 + krow] = kv.y;
            Ks[(kd + 2) * 128 + krow] = kv.z;
            Ks[(kd + 3) * 128 + krow] = kv.w;
            __syncthreads();
#pragma unroll
            for (int kk = 0; kk < 8; kk++) {
                float ra[8], rb[8];
                *(float4*)&ra[0] = *(const float4*)&Qs[(c * 8 + kk) * 128 + tr * 8];
                *(float4*)&ra[4] = *(const float4*)&Qs[(c * 8 + kk) * 128 + tr * 8 + 4];
                *(float4*)&rb[0] = *(const float4*)&Ks[kk * 128 + tc * 8];
                *(float4*)&rb[4] = *(const float4*)&Ks[kk * 128 + tc * 8 + 4];
#pragma unroll
                for (int i = 0; i < 8; i++)
#pragma unroll
                    for (int j = 0; j < 8; j++)
                        s[i][j] = fmaf(ra[i], rb[j], s[i][j]);
            }
        }

#pragma unroll
        for (int i = 0; i < 8; i++) {
            const float* br = bptr + (size_t)(tr * 8 + i) * LLEN + k0 + tc * 8;
            const float* gr = gptr + (size_t)(tr * 8 + i) * LLEN + k0 + tc * 8;
            float4 b0 = *(const float4*)br, b1 = *(const float4*)(br + 4);
            float4 g0 = *(const float4*)gr, g1 = *(const float4*)(gr + 4);
            s[i][0] += b0.x + g0.x; s[i][1] += b0.y + g0.y;
            s[i][2] += b0.z + g0.z; s[i][3] += b0.w + g0.w;
            s[i][4] += b1.x + g1.x; s[i][5] += b1.y + g1.y;
            s[i][6] += b1.z + g1.z; s[i][7] += b1.w + g1.w;
        }

#pragma unroll
        for (int i = 0; i < 8; i++) {
            float tm = s[i][0];
#pragma unroll
            for (int j = 1; j < 8; j++) tm = fmaxf(tm, s[i][j]);
#pragma unroll
            for (int off = 8; off > 0; off >>= 1)
                tm = fmaxf(tm, __shfl_xor_sync(0xffffffffu, tm, off));
            const float mn  = fmaxf(m_run[i], tm);
            const float fac = __expf(m_run[i] - mn);
            m_run[i] = mn;
            float ls = 0.f;
#pragma unroll
            for (int j = 0; j < 8; j++) {
                float p = __expf(s[i][j] - mn);
                s[i][j] = p;
                ls += p;
            }
            l_run[i] = l_run[i] * fac + ls;
            o[i][0] *= fac; o[i][1] *= fac; o[i][2] *= fac; o[i][3] *= fac;
        }

#pragma unroll
        for (int i = 0; i < 8; i++) {
            *(float4*)&Ps[(tr * 8 + i) * 128 + tc * 8] =
                make_float4(s[i][0], s[i][1], s[i][2], s[i][3]);
            *(float4*)&Ps[(tr * 8 + i) * 128 + tc * 8 + 4] =
                make_float4(s[i][4], s[i][5], s[i][6], s[i][7]);
        }
        __syncthreads();

#pragma unroll 4
        for (int c = 0; c < 128; c++) {
            float4 rv = *(const float4*)&Vs[c * 64 + tc * 4];
#pragma unroll
            for (int i = 0; i < 8; i++) {
                float p = Ps[(tr * 8 + i) * 128 + c];
                o[i][0] = fmaf(p, rv.x, o[i][0]);
                o[i][1] = fmaf(p, rv.y, o[i][1]);
                o[i][2] = fmaf(p, rv.z, o[i][2]);
                o[i][3] = fmaf(p, rv.w, o[i][3]);
            }
        }
        __syncthreads();
    }

    const int b = bh >> 4, h = bh & 15;
#pragma unroll
    for (int i = 0; i < 8; i++) {
        float lt = l_run[i];
#pragma unroll
        for (int off = 8; off > 0; off >>= 1)
            lt += __shfl_xor_sync(0xffffffffu, lt, off);
        const float inv = 1.0f / lt;
        const int qrow = q0 + tr * 8 + i;
        float4 ov = make_float4(o[i][0] * inv, o[i][1] * inv,
                                o[i][2] * inv, o[i][3] * inv);
        *(float4*)&g_ctx[(size_t)(b * LLEN + qrow) * DD + h * 64 + tc * 4] = ov;
    }
}

// ---------------- LayerNorm: grid 2048, 256 threads ----------------
__global__ __launch_bounds__(256)
void ln_kernel(const float* __restrict__ gamma, const float* __restrict__ beta,
               float* __restrict__ out)
{
    __shared__ float red[8];
    const int row = blockIdx.x, tid = threadIdx.x;
    const float4 xv = *(const float4*)&g_pre[(size_t)row * DD + tid * 4];

    float sv = xv.x + xv.y + xv.z + xv.w;
#pragma unroll
    for (int off = 16; off > 0; off >>= 1) sv += __shfl_xor_sync(0xffffffffu, sv, off);
    if ((tid & 31) == 0) red[tid >> 5] = sv;
    __syncthreads();
    float tot = 0.f;
#pragma unroll
    for (int w = 0; w < 8; w++) tot += red[w];
    const float mean = tot * (1.0f / 1024.0f);

    const float dx = xv.x - mean, dy = xv.y - mean, dz = xv.z - mean, dw = xv.w - mean;
    float ss = dx * dx + dy * dy + dz * dz + dw * dw;
    __syncthreads();
#pragma unroll
    for (int off = 16; off > 0; off >>= 1) ss += __shfl_xor_sync(0xffffffffu, ss, off);
    if ((tid & 31) == 0) red[tid >> 5] = ss;
    __syncthreads();
    float tot2 = 0.f;
#pragma unroll
    for (int w = 0; w < 8; w++) tot2 += red[w];
    const float rstd = rsqrtf(tot2 * (1.0f / 1024.0f) + 1e-6f);

    const float4 gv = *(const float4*)&gamma[tid * 4];
    const float4 bv = *(const float4*)&beta[tid * 4];
    float4 ov;
    ov.x = dx * rstd * gv.x + bv.x;
    ov.y = dy * rstd * gv.y + bv.y;
    ov.z = dz * rstd * gv.z + bv.z;
    ov.w = dw * rstd * gv.w + bv.w;
    *(float4*)&out[(size_t)row * DD + tid * 4] = ov;
}

// ---------------- launch ----------------
extern "C" void kernel_launch(void* const* d_in, const int* in_sizes, int n_in,
                              void* d_out, int out_size)
{
    const float* q     = (const float*)d_in[0];
    const float* k     = (const float*)d_in[1];
    const float* v     = (const float*)d_in[2];
    const float* bias  = (const float*)d_in[3];
    const float* gbias = (const float*)d_in[4];
    const float* wq    = (const float*)d_in[5];
    const float* bq    = (const float*)d_in[6];
    const float* wk    = (const float*)d_in[7];
    const float* bk    = (const float*)d_in[8];
    const float* wv    = (const float*)d_in[9];
    const float* bv    = (const float*)d_in[10];
    const float* wo    = (const float*)d_in[11];
    const float* bo    = (const float*)d_in[12];
    const float* ln_g  = (const float*)d_in[13];
    const float* ln_b  = (const float*)d_in[14];
    float* out = (float*)d_out;

    const int attn_smem = ATTN_SMEM_FLOATS * (int)sizeof(float);   // 135168 B
    cudaFuncSetAttribute(attn_kernel,
                         cudaFuncAttributeMaxDynamicSharedMemorySize, attn_smem);

    proj_kernel<<<dim3(8, 16, 3), 256>>>(q, k, v, wq, wk, wv, bq, bk, bv);
    attn_kernel<<<dim3(4, 64), 256, attn_smem>>>(bias, gbias);
    outproj_kernel<<<dim3(8, 16), 256>>>(wo, bo, q);
    ln_kernel<<<2048, 256>>>(ln_g, ln_b, out);
}

// round 8
// speedup vs baseline: 1.9969x; 1.2448x over previous
#include <cuda_runtime.h>

#define HH 16
#define LLEN 512
#define DD 1024
#define BB 4
#define BHN (BB*HH)      // 64
#define MR (BB*LLEN)     // 2048
#define SA 132           // proj smem row stride

// attention smem strides (in 32-bit words)
#define KS_STRIDE 68     // K tile [128 key][64 d]
#define VT_STRIDE 132    // V^T tile [64 dv][128 key]
#define PS_STRIDE 132    // per-warp P tile [16 q][128 key]
#define ATTN_SMEM_WORDS (128*KS_STRIDE + 64*VT_STRIDE + 8*16*PS_STRIDE)

// ---------------- scratch (no cudaMalloc allowed) ----------------
__device__ float g_qh[BHN * LLEN * 64];   // [b*H+h][l][64], Q pre-scaled by 1/8
__device__ float g_kh[BHN * LLEN * 64];
__device__ float g_vh[BHN * LLEN * 64];
__device__ float g_ctx[MR * DD];          // attention output, [b,l,h*64+dv]
__device__ float g_pre[MR * DD];          // pre-LayerNorm

// ---------------- tf32 helpers ----------------
__device__ __forceinline__ unsigned f2tf32(float f) {
    unsigned r;
    asm("cvt.rna.tf32.f32 %0, %1;" : "=r"(r) : "f"(f));
    return r;
}

__device__ __forceinline__ void mma_tf32(float (&c)[4], const unsigned (&a)[4],
                                         const unsigned (&b)[2]) {
    asm("mma.sync.aligned.m16n8k8.row.col.f32.tf32.tf32.f32 "
        "{%0,%1,%2,%3}, {%4,%5,%6,%7}, {%8,%9}, {%0,%1,%2,%3};"
        : "+f"(c[0]), "+f"(c[1]), "+f"(c[2]), "+f"(c[3])
        : "r"(a[0]), "r"(a[1]), "r"(a[2]), "r"(a[3]), "r"(b[0]), "r"(b[1]));
}

// ---------------- TF32 mma GEMM core (projections) ----------------
__device__ __forceinline__ void mma_core(const float* __restrict__ A,
                                         const float* __restrict__ W,
                                         float (&acc)[4][4][4])
{
    __shared__ unsigned As[32 * SA];   // [k][m], tf32 bits
    __shared__ unsigned Ws[32 * SA];   // [k][n], tf32 bits

    const int tid  = threadIdx.x;
    const int w    = tid >> 5, lane = tid & 31;
    const int g    = lane >> 2, t = lane & 3;
    const int wm   = (w & 1) * 64, wn = (w >> 1) * 32;
    const int m0   = blockIdx.y * 128, n0 = blockIdx.x * 128;

    const int ar  = tid >> 1,  akq = (tid & 1) * 16;
    const int wkr = tid >> 3,  wnq = (tid & 7) * 16;

    for (int k0 = 0; k0 < DD; k0 += 32) {
        float4 av[4], wv[4];
#pragma unroll
        for (int i = 0; i < 4; i++)
            av[i] = *(const float4*)&A[(size_t)(m0 + ar) * DD + k0 + akq + i * 4];
#pragma unroll
        for (int i = 0; i < 4; i++)
            wv[i] = *(const float4*)&W[(size_t)(k0 + wkr) * DD + n0 + wnq + i * 4];

        __syncthreads();
#pragma unroll
        for (int i = 0; i < 4; i++) {
            const float* p = (const float*)&av[i];
#pragma unroll
            for (int jj = 0; jj < 4; jj++)
                As[(akq + i * 4 + jj) * SA + ar] = f2tf32(p[jj]);
        }
#pragma unroll
        for (int i = 0; i < 4; i++) {
            const float* p = (const float*)&wv[i];
#pragma unroll
            for (int jj = 0; jj < 4; jj++)
                Ws[wkr * SA + wnq + i * 4 + jj] = f2tf32(p[jj]);
        }
        __syncthreads();

#pragma unroll
        for (int ks = 0; ks < 4; ks++) {
            const int kk = ks * 8;
            unsigned a[4][4], b[4][2];
#pragma unroll
            for (int mt = 0; mt < 4; mt++) {
                const int m = wm + mt * 16 + g;
                a[mt][0] = As[(kk + t) * SA + m];
                a[mt][1] = As[(kk + t) * SA + m + 8];
                a[mt][2] = As[(kk + t + 4) * SA + m];
                a[mt][3] = As[(kk + t + 4) * SA + m + 8];
            }
#pragma unroll
            for (int nt = 0; nt < 4; nt++) {
                const int n = wn + nt * 8 + g;
                b[nt][0] = Ws[(kk + t) * SA + n];
                b[nt][1] = Ws[(kk + t + 4) * SA + n];
            }
#pragma unroll
            for (int mt = 0; mt < 4; mt++)
#pragma unroll
                for (int nt = 0; nt < 4; nt++)
                    mma_tf32(acc[mt][nt], a[mt], b[nt]);
        }
    }
}

// ---------------- QKV projection: grid (8, 16, 3) ----------------
__global__ __launch_bounds__(256, 2)
void proj_kernel(const float* __restrict__ q, const float* __restrict__ k,
                 const float* __restrict__ v,
                 const float* __restrict__ wq, const float* __restrict__ wk,
                 const float* __restrict__ wv,
                 const float* __restrict__ bq, const float* __restrict__ bk,
                 const float* __restrict__ bv)
{
    const int z = blockIdx.z;
    const float* A    = (z == 0) ? q  : (z == 1) ? k  : v;
    const float* W    = (z == 0) ? wq : (z == 1) ? wk : wv;
    const float* bias = (z == 0) ? bq : (z == 1) ? bk : bv;
    float* out        = (z == 0) ? g_qh : (z == 1) ? g_kh : g_vh;
    const float scale = (z == 0) ? 0.125f : 1.0f;

    float acc[4][4][4];
#pragma unroll
    for (int mt = 0; mt < 4; mt++)
#pragma unroll
        for (int nt = 0; nt < 4; nt++)
#pragma unroll
            for (int i = 0; i < 4; i++) acc[mt][nt][i] = 0.f;

    mma_core(A, W, acc);

    const int tid = threadIdx.x;
    const int w = tid >> 5, lane = tid & 31;
    const int g = lane >> 2, t = lane & 3;
    const int wm = (w & 1) * 64, wn = (w >> 1) * 32;
    const int m0 = blockIdx.y * 128, n0 = blockIdx.x * 128;

#pragma unroll
    for (int mt = 0; mt < 4; mt++) {
        const int r0 = m0 + wm + mt * 16 + g;
#pragma unroll
        for (int nt = 0; nt < 4; nt++) {
            const int c0 = n0 + wn + nt * 8 + 2 * t;
#pragma unroll
            for (int e = 0; e < 4; e++) {
                const int r = r0 + (e >> 1) * 8;
                const int c = c0 + (e & 1);
                const int b = r >> 9, l = r & 511;
                const int h = c >> 6, d = c & 63;
                out[(size_t)(((b << 4) + h) * LLEN + l) * 64 + d] =
                    (acc[mt][nt][e] + bias[c]) * scale;
            }
        }
    }
}

// ---------------- output projection + bias + residual: grid (8, 16) ----------------
__global__ __launch_bounds__(256, 2)
void outproj_kernel(const float* __restrict__ wo, const float* __restrict__ bo,
                    const float* __restrict__ resid)
{
    float acc[4][4][4];
#pragma unroll
    for (int mt = 0; mt < 4; mt++)
#pragma unroll
        for (int nt = 0; nt < 4; nt++)
#pragma unroll
            for (int i = 0; i < 4; i++) acc[mt][nt][i] = 0.f;

    mma_core(g_ctx, wo, acc);

    const int tid = threadIdx.x;
    const int w = tid >> 5, lane = tid & 31;
    const int g = lane >> 2, t = lane & 3;
    const int wm = (w & 1) * 64, wn = (w >> 1) * 32;
    const int m0 = blockIdx.y * 128, n0 = blockIdx.x * 128;

#pragma unroll
    for (int mt = 0; mt < 4; mt++) {
        const int r0 = m0 + wm + mt * 16 + g;
#pragma unroll
        for (int nt = 0; nt < 4; nt++) {
            const int c0 = n0 + wn + nt * 8 + 2 * t;
#pragma unroll
            for (int e = 0; e < 4; e++) {
                const int r = r0 + (e >> 1) * 8;
                const int c = c0 + (e & 1);
                g_pre[(size_t)r * DD + c] =
                    acc[mt][nt][e] + bo[c] + resid[(size_t)r * DD + c];
            }
        }
    }
}

// ---------------- attention (TF32 mma): grid (4, 64), 256 threads ----------------
// 8 warps; warp w owns query rows [16w, 16w+16). Each warp computes its full
// S rows (nt=16 over 128 keys) -> softmax is warp-local (4-lane shfl).
__global__ __launch_bounds__(256, 1)
void attn_kernel(const float* __restrict__ bias, const float* __restrict__ gbias)
{
    extern __shared__ unsigned smu[];
    unsigned* Ks = smu;                       // [128 key][KS_STRIDE] tf32
    unsigned* Vt = Ks + 128 * KS_STRIDE;      // [64 dv][VT_STRIDE] tf32 (transposed)
    unsigned* Ps = Vt + 64 * VT_STRIDE;       // 8 x [16 q][PS_STRIDE] tf32

    const int tid  = threadIdx.x;
    const int w    = tid >> 5, lane = tid & 31;
    const int g    = lane >> 2, t = lane & 3;
    const int bh   = blockIdx.y;              // b*16 + h
    const int q0   = blockIdx.x * 128;
    unsigned* Pw   = Ps + w * 16 * PS_STRIDE;

    const float* kbase = g_kh + (size_t)bh * LLEN * 64;
    const float* vbase = g_vh + (size_t)bh * LLEN * 64;

    const int rowg = q0 + w * 16 + g;        // this thread's first query row
    const float* bp0 = bias  + (size_t)(bh * LLEN + rowg) * LLEN;
    const float* bp1 = bp0 + 8 * LLEN;
    const float* gp0 = gbias + (size_t)(bh * LLEN + rowg) * LLEN;
    const float* gp1 = gp0 + 8 * LLEN;

    // Q A-fragments in registers, reused across all key blocks
    unsigned aq[8][4];
    {
        const float* qr0 = g_qh + (size_t)(bh * LLEN + rowg) * 64;
        const float* qr1 = qr0 + 8 * 64;
#pragma unroll
        for (int ks = 0; ks < 8; ks++) {
            aq[ks][0] = f2tf32(qr0[ks * 8 + t]);
            aq[ks][1] = f2tf32(qr1[ks * 8 + t]);
            aq[ks][2] = f2tf32(qr0[ks * 8 + t + 4]);
            aq[ks][3] = f2tf32(qr1[ks * 8 + t + 4]);
        }
    }

    float m0r = -1e30f, m1r = -1e30f, l0 = 0.f, l1 = 0.f;
    float o[8][4];
#pragma unroll
    for (int nt = 0; nt < 8; nt++)
#pragma unroll
        for (int e = 0; e < 4; e++) o[nt][e] = 0.f;

    const int srow = tid >> 1;               // staging row 0..127
    const int sdq  = (tid & 1) * 4;

    for (int kb = 0; kb < 4; kb++) {
        const int k0 = kb * 128;

        // ---- stage K (k-major) and V^T (dv-major) as tf32 ----
#pragma unroll
        for (int c = 0; c < 8; c++) {
            float4 kv = *(const float4*)&kbase[(size_t)(k0 + srow) * 64 + c * 8 + sdq];
            unsigned* dst = &Ks[srow * KS_STRIDE + c * 8 + sdq];
            dst[0] = f2tf32(kv.x); dst[1] = f2tf32(kv.y);
            dst[2] = f2tf32(kv.z); dst[3] = f2tf32(kv.w);
            float4 vv = *(const float4*)&vbase[(size_t)(k0 + srow) * 64 + c * 8 + sdq];
            Vt[(c * 8 + sdq + 0) * VT_STRIDE + srow] = f2tf32(vv.x);
            Vt[(c * 8 + sdq + 1) * VT_STRIDE + srow] = f2tf32(vv.y);
            Vt[(c * 8 + sdq + 2) * VT_STRIDE + srow] = f2tf32(vv.z);
            Vt[(c * 8 + sdq + 3) * VT_STRIDE + srow] = f2tf32(vv.w);
        }
        __syncthreads();

        // ---- S = Q K^T : 16 fragments (this warp's 16 rows x 128 keys) ----
        float s[16][4];
#pragma unroll
        for (int nt = 0; nt < 16; nt++)
#pragma unroll
            for (int e = 0; e < 4; e++) s[nt][e] = 0.f;

#pragma unroll
        for (int ks = 0; ks < 8; ks++) {
#pragma unroll
            for (int nt = 0; nt < 16; nt++) {
                unsigned b[2];
                b[0] = Ks[(nt * 8 + g) * KS_STRIDE + ks * 8 + t];
                b[1] = Ks[(nt * 8 + g) * KS_STRIDE + ks * 8 + t + 4];
                mma_tf32(s[nt], aq[ks], b);
            }
        }

        // ---- add biases, find row maxima ----
        float mx0 = -1e30f, mx1 = -1e30f;
#pragma unroll
        for (int nt = 0; nt < 16; nt++) {
            const int c = k0 + nt * 8 + 2 * t;
            float2 b0 = *(const float2*)&bp0[c];
            float2 gb0 = *(const float2*)&gp0[c];
            float2 b1 = *(const float2*)&bp1[c];
            float2 gb1 = *(const float2*)&gp1[c];
            s[nt][0] += b0.x + gb0.x; s[nt][1] += b0.y + gb0.y;
            s[nt][2] += b1.x + gb1.x; s[nt][3] += b1.y + gb1.y;
            mx0 = fmaxf(mx0, fmaxf(s[nt][0], s[nt][1]));
            mx1 = fmaxf(mx1, fmaxf(s[nt][2], s[nt][3]));
        }
        mx0 = fmaxf(mx0, __shfl_xor_sync(0xffffffffu, mx0, 1));
        mx0 = fmaxf(mx0, __shfl_xor_sync(0xffffffffu, mx0, 2));
        mx1 = fmaxf(mx1, __shfl_xor_sync(0xffffffffu, mx1, 1));
        mx1 = fmaxf(mx1, __shfl_xor_sync(0xffffffffu, mx1, 2));

        const float mn0 = fmaxf(m0r, mx0), mn1 = fmaxf(m1r, mx1);
        const float fac0 = __expf(m0r - mn0), fac1 = __expf(m1r - mn1);
        m0r = mn0; m1r = mn1;

        // ---- exp, write P (tf32) to this warp's smem tile ----
        float ls0 = 0.f, ls1 = 0.f;
#pragma unroll
        for (int nt = 0; nt < 16; nt++) {
            float p0 = __expf(s[nt][0] - mn0);
            float p1 = __expf(s[nt][1] - mn0);
            float p2 = __expf(s[nt][2] - mn1);
            float p3 = __expf(s[nt][3] - mn1);
            ls0 += p0 + p1; ls1 += p2 + p3;
            unsigned* d0 = &Pw[g * PS_STRIDE + nt * 8 + 2 * t];
            d0[0] = f2tf32(p0); d0[1] = f2tf32(p1);
            unsigned* d1 = &Pw[(g + 8) * PS_STRIDE + nt * 8 + 2 * t];
            d1[0] = f2tf32(p2); d1[1] = f2tf32(p3);
        }
        l0 = l0 * fac0 + ls0;
        l1 = l1 * fac1 + ls1;
#pragma unroll
        for (int nt = 0; nt < 8; nt++) {
            o[nt][0] *= fac0; o[nt][1] *= fac0;
            o[nt][2] *= fac1; o[nt][3] *= fac1;
        }
        __syncwarp();

        // ---- O += P V ----
#pragma unroll
        for (int ks = 0; ks < 16; ks++) {
            unsigned ap[4];
            ap[0] = Pw[g * PS_STRIDE + ks * 8 + t];
            ap[1] = Pw[(g + 8) * PS_STRIDE + ks * 8 + t];
            ap[2] = Pw[g * PS_STRIDE + ks * 8 + t + 4];
            ap[3] = Pw[(g + 8) * PS_STRIDE + ks * 8 + t + 4];
#pragma unroll
            for (int nt = 0; nt < 8; nt++) {
                unsigned bv[2];
                bv[0] = Vt[(nt * 8 + g) * VT_STRIDE + ks * 8 + t];
                bv[1] = Vt[(nt * 8 + g) * VT_STRIDE + ks * 8 + t + 4];
                mma_tf32(o[nt], ap, bv);
            }
        }
        __syncthreads();   // Ks/Vt consumed; safe to restage next block
    }

    // ---- finalize: reduce row sums over the 4 t-lanes, normalize, store ----
    l0 += __shfl_xor_sync(0xffffffffu, l0, 1);
    l0 += __shfl_xor_sync(0xffffffffu, l0, 2);
    l1 += __shfl_xor_sync(0xffffffffu, l1, 1);
    l1 += __shfl_xor_sync(0xffffffffu, l1, 2);
    const float inv0 = 1.0f / l0, inv1 = 1.0f / l1;

    const int b = bh >> 4, h = bh & 15;
    float* c0 = &g_ctx[(size_t)(b * LLEN + rowg) * DD + h * 64];
    float* c1 = c0 + 8 * (size_t)DD;
#pragma unroll
    for (int nt = 0; nt < 8; nt++) {
        *(float2*)&c0[nt * 8 + 2 * t] = make_float2(o[nt][0] * inv0, o[nt][1] * inv0);
        *(float2*)&c1[nt * 8 + 2 * t] = make_float2(o[nt][2] * inv1, o[nt][3] * inv1);
    }
}

// ---------------- LayerNorm: grid 2048, 256 threads ----------------
__global__ __launch_bounds__(256)
void ln_kernel(const float* __restrict__ gamma, const float* __restrict__ beta,
               float* __restrict__ out)
{
    __shared__ float red[8];
    const int row = blockIdx.x, tid = threadIdx.x;
    const float4 xv = *(const float4*)&g_pre[(size_t)row * DD + tid * 4];

    float sv = xv.x + xv.y + xv.z + xv.w;
#pragma unroll
    for (int off = 16; off > 0; off >>= 1) sv += __shfl_xor_sync(0xffffffffu, sv, off);
    if ((tid & 31) == 0) red[tid >> 5] = sv;
    __syncthreads();
    float tot = 0.f;
#pragma unroll
    for (int w = 0; w < 8; w++) tot += red[w];
    const float mean = tot * (1.0f / 1024.0f);

    const float dx = xv.x - mean, dy = xv.y - mean, dz = xv.z - mean, dw = xv.w - mean;
    float ss = dx * dx + dy * dy + dz * dz + dw * dw;
    __syncthreads();
#pragma unroll
    for (int off = 16; off > 0; off >>= 1) ss += __shfl_xor_sync(0xffffffffu, ss, off);
    if ((tid & 31) == 0) red[tid >> 5] = ss;
    __syncthreads();
    float tot2 = 0.f;
#pragma unroll
    for (int w = 0; w < 8; w++) tot2 += red[w];
    const float rstd = rsqrtf(tot2 * (1.0f / 1024.0f) + 1e-6f);

    const float4 gv = *(const float4*)&gamma[tid * 4];
    const float4 bv = *(const float4*)&beta[tid * 4];
    float4 ov;
    ov.x = dx * rstd * gv.x + bv.x;
    ov.y = dy * rstd * gv.y + bv.y;
    ov.z = dz * rstd * gv.z + bv.z;
    ov.w = dw * rstd * gv.w + bv.w;
    *(float4*)&out[(size_t)row * DD + tid * 4] = ov;
}

// ---------------- launch ----------------
extern "C" void kernel_launch(void* const* d_in, const int* in_sizes, int n_in,
                              void* d_out, int out_size)
{
    const float* q     = (const float*)d_in[0];
    const float* k     = (const float*)d_in[1];
    const float* v     = (const float*)d_in[2];
    const float* bias  = (const float*)d_in[3];
    const float* gbias = (const float*)d_in[4];
    const float* wq    = (const float*)d_in[5];
    const float* bq    = (const float*)d_in[6];
    const float* wk    = (const float*)d_in[7];
    const float* bk    = (const float*)d_in[8];
    const float* wv    = (const float*)d_in[9];
    const float* bv    = (const float*)d_in[10];
    const float* wo    = (const float*)d_in[11];
    const float* bo    = (const float*)d_in[12];
    const float* ln_g  = (const float*)d_in[13];
    const float* ln_b  = (const float*)d_in[14];
    float* out = (float*)d_out;

    const int attn_smem = ATTN_SMEM_WORDS * (int)sizeof(unsigned);  // 136192 B
    cudaFuncSetAttribute(attn_kernel,
                         cudaFuncAttributeMaxDynamicSharedMemorySize, attn_smem);

    proj_kernel<<<dim3(8, 16, 3), 256>>>(q, k, v, wq, wk, wv, bq, bk, bv);
    attn_kernel<<<dim3(4, 64), 256, attn_smem>>>(bias, gbias);
    outproj_kernel<<<dim3(8, 16), 256>>>(wo, bo, q);
    ln_kernel<<<2048, 256>>>(ln_g, ln_b, out);
}

// round 11
// speedup vs baseline: 2.8760x; 1.4403x over previous
#include <cuda_runtime.h>

#define HH 16
#define LLEN 512
#define DD 1024
#define BB 4
#define BHN (BB*HH)      // 64
#define MR (BB*LLEN)     // 2048

// proj GEMM smem (words)
#define AS_STRIDE 36           // A tile row: 32 k-words + 4 pad
#define WS_STRIDE 132          // W tile row: 128 n-words + 4 pad
#define AS_WORDS (128*AS_STRIDE)   // 4608
#define WS_WORDS (32*WS_STRIDE)    // 4224
#define PROJ_SMEM_BYTES (2*(AS_WORDS + WS_WORDS)*4)   // 70656

// attention smem (words)
#define KV_STRIDE 68           // [128 key][64 d] + 4 pad
#define KV_WORDS (128*KV_STRIDE)   // 8704
#define PS_STRIDE 132
#define ATTN_SMEM_WORDS (4*KV_WORDS + 8*16*PS_STRIDE) // 51712
#define ATTN_SMEM_BYTES (ATTN_SMEM_WORDS*4)           // 206848

// ---------------- scratch (no cudaMalloc allowed) ----------------
__device__ float g_qh[BHN * LLEN * 64];   // [b*H+h][l][64], Q pre-scaled by 1/8
__device__ float g_kh[BHN * LLEN * 64];
__device__ float g_vh[BHN * LLEN * 64];
__device__ float g_ctx[MR * DD];          // attention output, [b,l,h*64+dv]
__device__ float g_pre[MR * DD];          // pre-LayerNorm

// ---------------- helpers ----------------
__device__ __forceinline__ void cpa16(unsigned dst, const void* src) {
    asm volatile("cp.async.cg.shared.global [%0], [%1], 16;" :: "r"(dst), "l"(src));
}
#define CP_COMMIT() asm volatile("cp.async.commit_group;")
#define CP_WAIT(N)  asm volatile("cp.async.wait_group %0;" :: "n"(N))

__device__ __forceinline__ unsigned sa32(const void* p) {
    return (unsigned)__cvta_generic_to_shared(p);
}

// tf32 mma, operands carry raw fp32 bits (HW truncates to tf32)
__device__ __forceinline__ void mma_tf32(float (&c)[4], const unsigned (&a)[4],
                                         const unsigned (&b)[2]) {
    asm("mma.sync.aligned.m16n8k8.row.col.f32.tf32.tf32.f32 "
        "{%0,%1,%2,%3}, {%4,%5,%6,%7}, {%8,%9}, {%0,%1,%2,%3};"
        : "+f"(c[0]), "+f"(c[1]), "+f"(c[2]), "+f"(c[3])
        : "r"(a[0]), "r"(a[1]), "r"(a[2]), "r"(a[3]), "r"(b[0]), "r"(b[1]));
}

// ---------------- TF32 mma GEMM core with cp.async double buffering ----------
// C[128x128] tile; 8 warps, warp tile 64x32; K-tile 32; A row-major smem,
// W k-major smem; raw fp32 bits consumed as tf32.
__device__ __forceinline__ void mma_core(const float* __restrict__ A,
                                         const float* __restrict__ W,
                                         float (&acc)[4][4][4])
{
    extern __shared__ unsigned dynsm[];
    unsigned* As = dynsm;                 // [2][AS_WORDS]
    unsigned* Ws = dynsm + 2 * AS_WORDS;  // [2][WS_WORDS]

    const int tid  = threadIdx.x;
    const int w    = tid >> 5, lane = tid & 31;
    const int g    = lane >> 2, t = lane & 3;
    const int wm   = (w & 1) * 64, wn = (w >> 1) * 32;
    const int m0   = blockIdx.y * 128, n0 = blockIdx.x * 128;

    // stage K-tile kt into buffer buf
    auto stage = [&](int kt, int buf) {
        const int k0 = kt * 32;
        unsigned* Ab = As + buf * AS_WORDS;
        unsigned* Wb = Ws + buf * WS_WORDS;
#pragma unroll
        for (int i = 0; i < 4; i++) {
            const int cid = i * 256 + tid;
            const int ar = cid >> 3, akw = (cid & 7) * 4;
            cpa16(sa32(Ab + ar * AS_STRIDE + akw),
                  &A[(size_t)(m0 + ar) * DD + k0 + akw]);
            const int wr = cid >> 5, wnw = (cid & 31) * 4;
            cpa16(sa32(Wb + wr * WS_STRIDE + wnw),
                  &W[(size_t)(k0 + wr) * DD + n0 + wnw]);
        }
    };

    stage(0, 0); CP_COMMIT();

    for (int kt = 0; kt < 32; kt++) {
        if (kt < 31) { stage(kt + 1, (kt + 1) & 1); CP_COMMIT(); CP_WAIT(1); }
        else         { CP_WAIT(0); }
        __syncthreads();

        const unsigned* Ab = As + (kt & 1) * AS_WORDS;
        const unsigned* Wb = Ws + (kt & 1) * WS_WORDS;
#pragma unroll
        for (int ks = 0; ks < 4; ks++) {
            const int kk = ks * 8;
            unsigned a[4][4], b[4][2];
#pragma unroll
            for (int mt = 0; mt < 4; mt++) {
                const int m = wm + mt * 16 + g;
                a[mt][0] = Ab[m * AS_STRIDE + kk + t];
                a[mt][1] = Ab[(m + 8) * AS_STRIDE + kk + t];
                a[mt][2] = Ab[m * AS_STRIDE + kk + t + 4];
                a[mt][3] = Ab[(m + 8) * AS_STRIDE + kk + t + 4];
            }
#pragma unroll
            for (int nt = 0; nt < 4; nt++) {
                const int n = wn + nt * 8 + g;
                b[nt][0] = Wb[(kk + t) * WS_STRIDE + n];
                b[nt][1] = Wb[(kk + t + 4) * WS_STRIDE + n];
            }
#pragma unroll
            for (int mt = 0; mt < 4; mt++)
#pragma unroll
                for (int nt = 0; nt < 4; nt++)
                    mma_tf32(acc[mt][nt], a[mt], b[nt]);
        }
        __syncthreads();
    }
}

// ---------------- QKV projection: grid (8, 16, 3) ----------------
__global__ __launch_bounds__(256, 2)
void proj_kernel(const float* __restrict__ q, const float* __restrict__ k,
                 const float* __restrict__ v,
                 const float* __restrict__ wq, const float* __restrict__ wk,
                 const float* __restrict__ wv,
                 const float* __restrict__ bq, const float* __restrict__ bk,
                 const float* __restrict__ bv)
{
    const int z = blockIdx.z;
    const float* A    = (z == 0) ? q  : (z == 1) ? k  : v;
    const float* W    = (z == 0) ? wq : (z == 1) ? wk : wv;
    const float* bias = (z == 0) ? bq : (z == 1) ? bk : bv;
    float* out        = (z == 0) ? g_qh : (z == 1) ? g_kh : g_vh;
    const float scale = (z == 0) ? 0.125f : 1.0f;   // fold 1/sqrt(64) into Q

    float acc[4][4][4];
#pragma unroll
    for (int mt = 0; mt < 4; mt++)
#pragma unroll
        for (int nt = 0; nt < 4; nt++)
#pragma unroll
            for (int i = 0; i < 4; i++) acc[mt][nt][i] = 0.f;

    mma_core(A, W, acc);

    const int tid = threadIdx.x;
    const int w = tid >> 5, lane = tid & 31;
    const int g = lane >> 2, t = lane & 3;
    const int wm = (w & 1) * 64, wn = (w >> 1) * 32;
    const int m0 = blockIdx.y * 128, n0 = blockIdx.x * 128;

#pragma unroll
    for (int mt = 0; mt < 4; mt++) {
        const int r0 = m0 + wm + mt * 16 + g;
#pragma unroll
        for (int nt = 0; nt < 4; nt++) {
            const int c0 = n0 + wn + nt * 8 + 2 * t;
#pragma unroll
            for (int e = 0; e < 4; e++) {
                const int r = r0 + (e >> 1) * 8;
                const int c = c0 + (e & 1);
                const int b = r >> 9, l = r & 511;
                const int h = c >> 6, d = c & 63;
                out[(size_t)(((b << 4) + h) * LLEN + l) * 64 + d] =
                    (acc[mt][nt][e] + bias[c]) * scale;
            }
        }
    }
}

// ---------------- output projection + bias + residual: grid (8, 16) ----------------
__global__ __launch_bounds__(256, 2)
void outproj_kernel(const float* __restrict__ wo, const float* __restrict__ bo,
                    const float* __restrict__ resid)
{
    float acc[4][4][4];
#pragma unroll
    for (int mt = 0; mt < 4; mt++)
#pragma unroll
        for (int nt = 0; nt < 4; nt++)
#pragma unroll
            for (int i = 0; i < 4; i++) acc[mt][nt][i] = 0.f;

    mma_core(g_ctx, wo, acc);

    const int tid = threadIdx.x;
    const int w = tid >> 5, lane = tid & 31;
    const int g = lane >> 2, t = lane & 3;
    const int wm = (w & 1) * 64, wn = (w >> 1) * 32;
    const int m0 = blockIdx.y * 128, n0 = blockIdx.x * 128;

#pragma unroll
    for (int mt = 0; mt < 4; mt++) {
        const int r0 = m0 + wm + mt * 16 + g;
#pragma unroll
        for (int nt = 0; nt < 4; nt++) {
            const int c0 = n0 + wn + nt * 8 + 2 * t;
#pragma unroll
            for (int e = 0; e < 4; e++) {
                const int r = r0 + (e >> 1) * 8;
                const int c = c0 + (e & 1);
                g_pre[(size_t)r * DD + c] =
                    acc[mt][nt][e] + bo[c] + resid[(size_t)r * DD + c];
            }
        }
    }
}

// ---------------- attention (TF32 mma + cp.async): grid (4, 64), 256 threads ----
// 8 warps; warp w owns query rows [16w, 16w+16); softmax is warp-local.
// K and V staged natural [key][64] at stride 68 (conflict-free fragments),
// double-buffered across the 4 key blocks.
__global__ __launch_bounds__(256, 1)
void attn_kernel(const float* __restrict__ bias, const float* __restrict__ gbias)
{
    extern __shared__ unsigned smu[];
    unsigned* Ksm = smu;                       // [2][KV_WORDS]
    unsigned* Vsm = smu + 2 * KV_WORDS;        // [2][KV_WORDS]
    unsigned* Ps  = smu + 4 * KV_WORDS;        // 8 x [16 q][PS_STRIDE]

    const int tid  = threadIdx.x;
    const int w    = tid >> 5, lane = tid & 31;
    const int g    = lane >> 2, t = lane & 3;
    const int bh   = blockIdx.y;               // b*16 + h
    const int q0   = blockIdx.x * 128;
    unsigned* Pw   = Ps + w * 16 * PS_STRIDE;

    const float* kbase = g_kh + (size_t)bh * LLEN * 64;
    const float* vbase = g_vh + (size_t)bh * LLEN * 64;

    const int rowg = q0 + w * 16 + g;
    const float* bp0 = bias  + (size_t)(bh * LLEN + rowg) * LLEN;
    const float* bp1 = bp0 + 8 * LLEN;
    const float* gp0 = gbias + (size_t)(bh * LLEN + rowg) * LLEN;
    const float* gp1 = gp0 + 8 * LLEN;

    // stage key-block kb (K and V) into buffer buf
    auto stage = [&](int kb, int buf) {
        const int k0 = kb * 128;
        unsigned* Kb = Ksm + buf * KV_WORDS;
        unsigned* Vb = Vsm + buf * KV_WORDS;
#pragma unroll
        for (int i = 0; i < 8; i++) {
            const int cid = i * 256 + tid;
            const int row = cid >> 4, dw = (cid & 15) * 4;
            cpa16(sa32(Kb + row * KV_STRIDE + dw),
                  &kbase[(size_t)(k0 + row) * 64 + dw]);
            cpa16(sa32(Vb + row * KV_STRIDE + dw),
                  &vbase[(size_t)(k0 + row) * 64 + dw]);
        }
    };

    // Q A-fragments in registers (raw fp32 bits), reused across key blocks
    unsigned aq[8][4];
    {
        const float* qr0 = g_qh + (size_t)(bh * LLEN + rowg) * 64;
        const float* qr1 = qr0 + 8 * 64;
#pragma unroll
        for (int ks = 0; ks < 8; ks++) {
            aq[ks][0] = __float_as_uint(qr0[ks * 8 + t]);
            aq[ks][1] = __float_as_uint(qr1[ks * 8 + t]);
            aq[ks][2] = __float_as_uint(qr0[ks * 8 + t + 4]);
            aq[ks][3] = __float_as_uint(qr1[ks * 8 + t + 4]);
        }
    }

    float m0r = -1e30f, m1r = -1e30f, l0 = 0.f, l1 = 0.f;
    float o[8][4];
#pragma unroll
    for (int nt = 0; nt < 8; nt++)
#pragma unroll
        for (int e = 0; e < 4; e++) o[nt][e] = 0.f;

    stage(0, 0); CP_COMMIT();

    for (int kb = 0; kb < 4; kb++) {
        const int k0 = kb * 128;
        if (kb < 3) { stage(kb + 1, (kb + 1) & 1); CP_COMMIT(); CP_WAIT(1); }
        else        { CP_WAIT(0); }
        __syncthreads();

        const unsigned* Kb = Ksm + (kb & 1) * KV_WORDS;
        const unsigned* Vb = Vsm + (kb & 1) * KV_WORDS;

        // ---- S = Q K^T : this warp's 16 rows x 128 keys ----
        float s[16][4];
#pragma unroll
        for (int nt = 0; nt < 16; nt++)
#pragma unroll
            for (int e = 0; e < 4; e++) s[nt][e] = 0.f;

#pragma unroll
        for (int ks = 0; ks < 8; ks++) {
#pragma unroll
            for (int nt = 0; nt < 16; nt++) {
                unsigned b[2];
                b[0] = Kb[(nt * 8 + g) * KV_STRIDE + ks * 8 + t];
                b[1] = Kb[(nt * 8 + g) * KV_STRIDE + ks * 8 + t + 4];
                mma_tf32(s[nt], aq[ks], b);
            }
        }

        // ---- add biases, find row maxima ----
        float mx0 = -1e30f, mx1 = -1e30f;
#pragma unroll
        for (int nt = 0; nt < 16; nt++) {
            const int c = k0 + nt * 8 + 2 * t;
            float2 b0 = *(const float2*)&bp0[c];
            float2 gb0 = *(const float2*)&gp0[c];
            float2 b1 = *(const float2*)&bp1[c];
            float2 gb1 = *(const float2*)&gp1[c];
            s[nt][0] += b0.x + gb0.x; s[nt][1] += b0.y + gb0.y;
            s[nt][2] += b1.x + gb1.x; s[nt][3] += b1.y + gb1.y;
            mx0 = fmaxf(mx0, fmaxf(s[nt][0], s[nt][1]));
            mx1 = fmaxf(mx1, fmaxf(s[nt][2], s[nt][3]));
        }
        mx0 = fmaxf(mx0, __shfl_xor_sync(0xffffffffu, mx0, 1));
        mx0 = fmaxf(mx0, __shfl_xor_sync(0xffffffffu, mx0, 2));
        mx1 = fmaxf(mx1, __shfl_xor_sync(0xffffffffu, mx1, 1));
        mx1 = fmaxf(mx1, __shfl_xor_sync(0xffffffffu, mx1, 2));

        const float mn0 = fmaxf(m0r, mx0), mn1 = fmaxf(m1r, mx1);
        const float fac0 = __expf(m0r - mn0), fac1 = __expf(m1r - mn1);
        m0r = mn0; m1r = mn1;

        // ---- exp, write P (raw bits) to this warp's smem tile ----
        float ls0 = 0.f, ls1 = 0.f;
#pragma unroll
        for (int nt = 0; nt < 16; nt++) {
            float p0 = __expf(s[nt][0] - mn0);
            float p1 = __expf(s[nt][1] - mn0);
            float p2 = __expf(s[nt][2] - mn1);
            float p3 = __expf(s[nt][3] - mn1);
            ls0 += p0 + p1; ls1 += p2 + p3;
            unsigned* d0 = &Pw[g * PS_STRIDE + nt * 8 + 2 * t];
            d0[0] = __float_as_uint(p0); d0[1] = __float_as_uint(p1);
            unsigned* d1 = &Pw[(g + 8) * PS_STRIDE + nt * 8 + 2 * t];
            d1[0] = __float_as_uint(p2); d1[1] = __float_as_uint(p3);
        }
        l0 = l0 * fac0 + ls0;
        l1 = l1 * fac1 + ls1;
#pragma unroll
        for (int nt = 0; nt < 8; nt++) {
            o[nt][0] *= fac0; o[nt][1] *= fac0;
            o[nt][2] *= fac1; o[nt][3] *= fac1;
        }
        __syncwarp();

        // ---- O += P V  (V natural [key][dv], conflict-free) ----
#pragma unroll
        for (int ks = 0; ks < 16; ks++) {
            unsigned ap[4];
            ap[0] = Pw[g * PS_STRIDE + ks * 8 + t];
            ap[1] = Pw[(g + 8) * PS_STRIDE + ks * 8 + t];
            ap[2] = Pw[g * PS_STRIDE + ks * 8 + t + 4];
            ap[3] = Pw[(g + 8) * PS_STRIDE + ks * 8 + t + 4];
#pragma unroll
            for (int nt = 0; nt < 8; nt++) {
                unsigned bv[2];
                bv[0] = Vb[(ks * 8 + t) * KV_STRIDE + nt * 8 + g];
                bv[1] = Vb[(ks * 8 + t + 4) * KV_STRIDE + nt * 8 + g];
                mma_tf32(o[nt], ap, bv);
            }
        }
        __syncthreads();   // this buffer is free for prefetch two iters later
    }

    // ---- finalize ----
    l0 += __shfl_xor_sync(0xffffffffu, l0, 1);
    l0 += __shfl_xor_sync(0xffffffffu, l0, 2);
    l1 += __shfl_xor_sync(0xffffffffu, l1, 1);
    l1 += __shfl_xor_sync(0xffffffffu, l1, 2);
    const float inv0 = 1.0f / l0, inv1 = 1.0f / l1;

    const int b = bh >> 4, h = bh & 15;
    float* c0 = &g_ctx[(size_t)(b * LLEN + rowg) * DD + h * 64];
    float* c1 = c0 + 8 * (size_t)DD;
#pragma unroll
    for (int nt = 0; nt < 8; nt++) {
        *(float2*)&c0[nt * 8 + 2 * t] = make_float2(o[nt][0] * inv0, o[nt][1] * inv0);
        *(float2*)&c1[nt * 8 + 2 * t] = make_float2(o[nt][2] * inv1, o[nt][3] * inv1);
    }
}

// ---------------- LayerNorm: grid 2048, 256 threads ----------------
__global__ __launch_bounds__(256)
void ln_kernel(const float* __restrict__ gamma, const float* __restrict__ beta,
               float* __restrict__ out)
{
    __shared__ float red[8];
    const int row = blockIdx.x, tid = threadIdx.x;
    const float4 xv = *(const float4*)&g_pre[(size_t)row * DD + tid * 4];

    float sv = xv.x + xv.y + xv.z + xv.w;
#pragma unroll
    for (int off = 16; off > 0; off >>= 1) sv += __shfl_xor_sync(0xffffffffu, sv, off);
    if ((tid & 31) == 0) red[tid >> 5] = sv;
    __syncthreads();
    float tot = 0.f;
#pragma unroll
    for (int w = 0; w < 8; w++) tot += red[w];
    const float mean = tot * (1.0f / 1024.0f);

    const float dx = xv.x - mean, dy = xv.y - mean, dz = xv.z - mean, dw = xv.w - mean;
    float ss = dx * dx + dy * dy + dz * dz + dw * dw;
    __syncthreads();
#pragma unroll
    for (int off = 16; off > 0; off >>= 1) ss += __shfl_xor_sync(0xffffffffu, ss, off);
    if ((tid & 31) == 0) red[tid >> 5] = ss;
    __syncthreads();
    float tot2 = 0.f;
#pragma unroll
    for (int w = 0; w < 8; w++) tot2 += red[w];
    const float rstd = rsqrtf(tot2 * (1.0f / 1024.0f) + 1e-6f);

    const float4 gv = *(const float4*)&gamma[tid * 4];
    const float4 bv = *(const float4*)&beta[tid * 4];
    float4 ov;
    ov.x = dx * rstd * gv.x + bv.x;
    ov.y = dy * rstd * gv.y + bv.y;
    ov.z = dz * rstd * gv.z + bv.z;
    ov.w = dw * rstd * gv.w + bv.w;
    *(float4*)&out[(size_t)row * DD + tid * 4] = ov;
}

// ---------------- launch ----------------
extern "C" void kernel_launch(void* const* d_in, const int* in_sizes, int n_in,
                              void* d_out, int out_size)
{
    const float* q     = (const float*)d_in[0];
    const float* k     = (const float*)d_in[1];
    const float* v     = (const float*)d_in[2];
    const float* bias  = (const float*)d_in[3];
    const float* gbias = (const float*)d_in[4];
    const float* wq    = (const float*)d_in[5];
    const float* bq    = (const float*)d_in[6];
    const float* wk    = (const float*)d_in[7];
    const float* bk    = (const float*)d_in[8];
    const float* wv    = (const float*)d_in[9];
    const float* bv    = (const float*)d_in[10];
    const float* wo    = (const float*)d_in[11];
    const float* bo    = (const float*)d_in[12];
    const float* ln_g  = (const float*)d_in[13];
    const float* ln_b  = (const float*)d_in[14];
    float* out = (float*)d_out;

    cudaFuncSetAttribute(proj_kernel,
                         cudaFuncAttributeMaxDynamicSharedMemorySize, PROJ_SMEM_BYTES);
    cudaFuncSetAttribute(outproj_kernel,
                         cudaFuncAttributeMaxDynamicSharedMemorySize, PROJ_SMEM_BYTES);
    cudaFuncSetAttribute(attn_kernel,
                         cudaFuncAttributeMaxDynamicSharedMemorySize, ATTN_SMEM_BYTES);

    proj_kernel<<<dim3(8, 16, 3), 256, PROJ_SMEM_BYTES>>>(q, k, v, wq, wk, wv, bq, bk, bv);
    attn_kernel<<<dim3(4, 64), 256, ATTN_SMEM_BYTES>>>(bias, gbias);
    outproj_kernel<<<dim3(8, 16), 256, PROJ_SMEM_BYTES>>>(wo, bo, q);
    ln_kernel<<<2048, 256>>>(ln_g, ln_b, out);
}

// round 13
// speedup vs baseline: 4.5382x; 1.5779x over previous
#include <cuda_runtime.h>
#include <cuda_fp16.h>
#include <cstdint>

#define HH 16
#define LLEN 512
#define DD 1024
#define BB 4
#define BHN (BB*HH)      // 64
#define MR (BB*LLEN)     // 2048

// ---------------- scratch (no cudaMalloc allowed) ----------------
__device__ __half g_q16[MR * DD];        // fp16 copies of inputs
__device__ __half g_k16[MR * DD];
__device__ __half g_v16[MR * DD];
__device__ __half g_wth[4 * DD * DD];    // fp16 transposed weights [z][n][k]
__device__ __half g_qh[BHN * LLEN * 64]; // [bh][l][dk], pre-scaled by 1/8
__device__ __half g_kh[BHN * LLEN * 64]; // [bh][l][dk]
__device__ __half g_vt[BHN * 64 * LLEN]; // [bh][dv][l]  (transposed V)
__device__ __half g_ctx[MR * DD];        // attention output fp16
__device__ float  g_pre[MR * DD];        // pre-LayerNorm fp32

// ---------------- helpers ----------------
__device__ __forceinline__ void cpa16(unsigned dst, const void* src) {
    asm volatile("cp.async.cg.shared.global [%0], [%1], 16;" :: "r"(dst), "l"(src));
}
#define CP_COMMIT() asm volatile("cp.async.commit_group;")
#define CP_WAIT(N)  asm volatile("cp.async.wait_group %0;" :: "n"(N))

__device__ __forceinline__ unsigned sa32(const void* p) {
    return (unsigned)__cvta_generic_to_shared(p);
}

// fp16 mma m16n8k16, fp32 accumulate
__device__ __forceinline__ void mma16(float (&c)[4], const unsigned (&a)[4],
                                      const unsigned (&b)[2]) {
    asm("mma.sync.aligned.m16n8k16.row.col.f32.f16.f16.f32 "
        "{%0,%1,%2,%3}, {%4,%5,%6,%7}, {%8,%9}, {%0,%1,%2,%3};"
        : "+f"(c[0]), "+f"(c[1]), "+f"(c[2]), "+f"(c[3])
        : "r"(a[0]), "r"(a[1]), "r"(a[2]), "r"(a[3]), "r"(b[0]), "r"(b[1]));
}

__device__ __forceinline__ unsigned pack_h2(float a, float b) {
    __half2 h = __floats2half2_rn(a, b);
    return *reinterpret_cast<unsigned*>(&h);
}

// ---------------- input convert: fp32 -> fp16 ----------------
__global__ __launch_bounds__(256)
void convert_in(const float* __restrict__ q, const float* __restrict__ k,
                const float* __restrict__ v)
{
    const int i4 = (blockIdx.x * 256 + threadIdx.x) * 4;
    float4 a = *(const float4*)&q[i4];
    *(__half2*)&g_q16[i4]     = __floats2half2_rn(a.x, a.y);
    *(__half2*)&g_q16[i4 + 2] = __floats2half2_rn(a.z, a.w);
    float4 b = *(const float4*)&k[i4];
    *(__half2*)&g_k16[i4]     = __floats2half2_rn(b.x, b.y);
    *(__half2*)&g_k16[i4 + 2] = __floats2half2_rn(b.z, b.w);
    float4 c = *(const float4*)&v[i4];
    *(__half2*)&g_v16[i4]     = __floats2half2_rn(c.x, c.y);
    *(__half2*)&g_v16[i4 + 2] = __floats2half2_rn(c.z, c.w);
}

// ---------------- weight transpose+convert: g_wth[z][n][k] = w_z[k][n] -------
__global__ __launch_bounds__(256)
void transpose_w(const float* __restrict__ wq, const float* __restrict__ wk,
                 const float* __restrict__ wv, const float* __restrict__ wo)
{
    __shared__ float t[32][33];
    const int z = blockIdx.z;
    const float* src = (z == 0) ? wq : (z == 1) ? wk : (z == 2) ? wv : wo;
    __half* dst = g_wth + (size_t)z * DD * DD;
    const int x = blockIdx.x * 32, y = blockIdx.y * 32;   // x: n base, y: k base
    const int tx = threadIdx.x & 31, ty = threadIdx.x >> 5;
#pragma unroll
    for (int i = 0; i < 4; i++)
        t[ty + 8 * i][tx] = src[(size_t)(y + ty + 8 * i) * DD + x + tx];
    __syncthreads();
#pragma unroll
    for (int i = 0; i < 4; i++)
        dst[(size_t)(x + ty + 8 * i) * DD + y + tx] = __float2half(t[tx][ty + 8 * i]);
}

// ---------------- FP16 GEMM: C[128x128] tile, K=1024 in 16 chunks of 64 ------
// smem rows: 64 halves data + 8 pad = 72 halves = 144 B (16B-aligned, bank-clean)
#define GA_STRIDE 72
#define GA_HALF   (128 * GA_STRIDE)          // halves per buffer (9216)
#define GEMM_SMEM_BYTES (4 * GA_HALF * 2)    // A0 A1 B0 B1 = 73728

__global__ __launch_bounds__(256)
void gemm16(int is_outproj, const float* __restrict__ resid,
            const float* __restrict__ b0p, const float* __restrict__ b1p,
            const float* __restrict__ b2p)
{
    extern __shared__ __half smh[];
    __half* As = smh;                  // [2][GA_HALF]
    __half* Bs = smh + 2 * GA_HALF;    // [2][GA_HALF]

    const int tid = threadIdx.x;
    const int w = tid >> 5, lane = tid & 31;
    const int g = lane >> 2, t = lane & 3;
    const int wm = (w & 1) * 64, wn = (w >> 1) * 32;
    const int m0 = blockIdx.y * 128, n0 = blockIdx.x * 128;
    const int z = blockIdx.z;

    const __half* Ap = is_outproj ? g_ctx
                     : (z == 0) ? g_q16 : (z == 1) ? g_k16 : g_v16;
    const __half* Bt = g_wth + (size_t)(is_outproj ? 3 : z) * DD * DD;
    const float* bias = is_outproj ? b0p : (z == 0) ? b0p : (z == 1) ? b1p : b2p;

    auto stage = [&](int kt, int buf) {
        const int k0 = kt * 64;
        const unsigned ab = sa32(As + buf * GA_HALF);
        const unsigned bb = sa32(Bs + buf * GA_HALF);
#pragma unroll
        for (int i = 0; i < 4; i++) {
            const int id = i * 256 + tid;
            const int row = id >> 3, c16 = id & 7;
            cpa16(ab + row * 144 + c16 * 16, Ap + (size_t)(m0 + row) * DD + k0 + c16 * 8);
            cpa16(bb + row * 144 + c16 * 16, Bt + (size_t)(n0 + row) * DD + k0 + c16 * 8);
        }
    };

    float acc[4][4][4];
#pragma unroll
    for (int mt = 0; mt < 4; mt++)
#pragma unroll
        for (int nt = 0; nt < 4; nt++)
#pragma unroll
            for (int e = 0; e < 4; e++) acc[mt][nt][e] = 0.f;

    stage(0, 0); CP_COMMIT();

    for (int kt = 0; kt < 16; kt++) {
        if (kt < 15) { stage(kt + 1, (kt + 1) & 1); CP_COMMIT(); CP_WAIT(1); }
        else         { CP_WAIT(0); }
        __syncthreads();

        const unsigned* Au = (const unsigned*)(As + (kt & 1) * GA_HALF);
        const unsigned* Bu = (const unsigned*)(Bs + (kt & 1) * GA_HALF);
#pragma unroll
        for (int ks = 0; ks < 4; ks++) {
            unsigned a[4][4], b[4][2];
#pragma unroll
            for (int mt = 0; mt < 4; mt++) {
                const int r = wm + mt * 16 + g;
                a[mt][0] = Au[r * 36 + 8 * ks + t];
                a[mt][1] = Au[(r + 8) * 36 + 8 * ks + t];
                a[mt][2] = Au[r * 36 + 8 * ks + t + 4];
                a[mt][3] = Au[(r + 8) * 36 + 8 * ks + t + 4];
            }
#pragma unroll
            for (int nt = 0; nt < 4; nt++) {
                const int c = wn + nt * 8 + g;
                b[nt][0] = Bu[c * 36 + 8 * ks + t];
                b[nt][1] = Bu[c * 36 + 8 * ks + t + 4];
            }
#pragma unroll
            for (int mt = 0; mt < 4; mt++)
#pragma unroll
                for (int nt = 0; nt < 4; nt++)
                    mma16(acc[mt][nt], a[mt], b[nt]);
        }
        __syncthreads();
    }

    // epilogue
#pragma unroll
    for (int mt = 0; mt < 4; mt++) {
        const int r0 = m0 + wm + mt * 16 + g;
#pragma unroll
        for (int nt = 0; nt < 4; nt++) {
            const int c0 = n0 + wn + nt * 8 + 2 * t;
#pragma unroll
            for (int e = 0; e < 4; e++) {
                const int r = r0 + (e >> 1) * 8;
                const int c = c0 + (e & 1);
                const float val = acc[mt][nt][e] + bias[c];
                if (is_outproj) {
                    g_pre[(size_t)r * DD + c] = val + resid[(size_t)r * DD + c];
                } else {
                    const int b = r >> 9, l = r & 511;
                    const int h = c >> 6, d = c & 63;
                    const int bh = (b << 4) + h;
                    if (z == 0)
                        g_qh[(size_t)(bh * LLEN + l) * 64 + d] = __float2half(val * 0.125f);
                    else if (z == 1)
                        g_kh[(size_t)(bh * LLEN + l) * 64 + d] = __float2half(val);
                    else
                        g_vt[(size_t)(bh * 64 + d) * LLEN + l] = __float2half(val);
                }
            }
        }
    }
}

// ---------------- attention (fp16 mma + cp.async): grid (4, 64) ---------------
// K tile [128 key][72h] (144 B rows); V^T tile [64 dv][136h] (272 B rows).
#define KT_STRIDE_H 72
#define KT_HALF (128 * KT_STRIDE_H)      // 9216
#define VT_STRIDE_H 136
#define VT_HALF (64 * VT_STRIDE_H)       // 8704
#define ATTN_SMEM_BYTES ((2*KT_HALF + 2*VT_HALF) * 2)   // 71680

__global__ __launch_bounds__(256, 1)
void attn_kernel(const float* __restrict__ bias, const float* __restrict__ gbias)
{
    extern __shared__ __half smh[];
    __half* Ksm = smh;                   // [2][KT_HALF]
    __half* Vsm = smh + 2 * KT_HALF;     // [2][VT_HALF]

    const int tid = threadIdx.x;
    const int w = tid >> 5, lane = tid & 31;
    const int g = lane >> 2, t = lane & 3;
    const int bh = blockIdx.y;           // b*16 + h
    const int q0 = blockIdx.x * 128;

    const __half* kbase = g_kh + (size_t)bh * LLEN * 64;
    const __half* vtb   = g_vt + (size_t)bh * 64 * LLEN;

    const int rowg = q0 + w * 16 + g;
    const float* bp0 = bias  + (size_t)(bh * LLEN + rowg) * LLEN;
    const float* bp1 = bp0 + 8 * LLEN;
    const float* gp0 = gbias + (size_t)(bh * LLEN + rowg) * LLEN;
    const float* gp1 = gp0 + 8 * LLEN;

    auto stage = [&](int kb, int buf) {
        const int k0 = kb * 128;
        const unsigned kbm = sa32(Ksm + buf * KT_HALF);
        const unsigned vbm = sa32(Vsm + buf * VT_HALF);
#pragma unroll
        for (int i = 0; i < 4; i++) {
            const int id = i * 256 + tid;
            const int krow = id >> 3, kc = id & 7;       // K: 128 rows x 8 chunks
            cpa16(kbm + krow * 144 + kc * 16,
                  kbase + (size_t)(k0 + krow) * 64 + kc * 8);
            const int vrow = id >> 4, vc = id & 15;      // V^T: 64 rows x 16 chunks
            cpa16(vbm + vrow * 272 + vc * 16,
                  vtb + (size_t)vrow * LLEN + k0 + vc * 8);
        }
    };

    // Q A-fragments (fp16 pairs), reused across key blocks
    unsigned aq[4][4];
    {
        const __half* qr0 = g_qh + (size_t)(bh * LLEN + rowg) * 64;
        const __half* qr1 = qr0 + 8 * 64;
#pragma unroll
        for (int ks = 0; ks < 4; ks++) {
            aq[ks][0] = *(const unsigned*)&qr0[16 * ks + 2 * t];
            aq[ks][1] = *(const unsigned*)&qr1[16 * ks + 2 * t];
            aq[ks][2] = *(const unsigned*)&qr0[16 * ks + 2 * t + 8];
            aq[ks][3] = *(const unsigned*)&qr1[16 * ks + 2 * t + 8];
        }
    }

    float m0r = -1e30f, m1r = -1e30f, l0 = 0.f, l1 = 0.f;
    float o[8][4];
#pragma unroll
    for (int nt = 0; nt < 8; nt++)
#pragma unroll
        for (int e = 0; e < 4; e++) o[nt][e] = 0.f;

    stage(0, 0); CP_COMMIT();

    for (int kb = 0; kb < 4; kb++) {
        const int k0 = kb * 128;
        if (kb < 3) { stage(kb + 1, (kb + 1) & 1); CP_COMMIT(); CP_WAIT(1); }
        else        { CP_WAIT(0); }
        __syncthreads();

        const unsigned* Ku = (const unsigned*)(Ksm + (kb & 1) * KT_HALF);
        const unsigned* Vu = (const unsigned*)(Vsm + (kb & 1) * VT_HALF);

        // ---- S = Q K^T : 16 c-fragments (16 q rows x 128 keys) ----
        float s[16][4];
#pragma unroll
        for (int nt = 0; nt < 16; nt++)
#pragma unroll
            for (int e = 0; e < 4; e++) s[nt][e] = 0.f;

#pragma unroll
        for (int ks = 0; ks < 4; ks++) {
#pragma unroll
            for (int nt = 0; nt < 16; nt++) {
                unsigned b[2];
                b[0] = Ku[(nt * 8 + g) * 36 + 8 * ks + t];
                b[1] = Ku[(nt * 8 + g) * 36 + 8 * ks + t + 4];
                mma16(s[nt], aq[ks], b);
            }
        }

        // ---- add biases, find row maxima ----
        float mx0 = -1e30f, mx1 = -1e30f;
#pragma unroll
        for (int nt = 0; nt < 16; nt++) {
            const int c = k0 + nt * 8 + 2 * t;
            float2 b0 = *(const float2*)&bp0[c];
            float2 gb0 = *(const float2*)&gp0[c];
            float2 b1 = *(const float2*)&bp1[c];
            float2 gb1 = *(const float2*)&gp1[c];
            s[nt][0] += b0.x + gb0.x; s[nt][1] += b0.y + gb0.y;
            s[nt][2] += b1.x + gb1.x; s[nt][3] += b1.y + gb1.y;
            mx0 = fmaxf(mx0, fmaxf(s[nt][0], s[nt][1]));
            mx1 = fmaxf(mx1, fmaxf(s[nt][2], s[nt][3]));
        }
        mx0 = fmaxf(mx0, __shfl_xor_sync(0xffffffffu, mx0, 1));
        mx0 = fmaxf(mx0, __shfl_xor_sync(0xffffffffu, mx0, 2));
        mx1 = fmaxf(mx1, __shfl_xor_sync(0xffffffffu, mx1, 1));
        mx1 = fmaxf(mx1, __shfl_xor_sync(0xffffffffu, mx1, 2));

        const float mn0 = fmaxf(m0r, mx0), mn1 = fmaxf(m1r, mx1);
        const float fac0 = __expf(m0r - mn0), fac1 = __expf(m1r - mn1);
        m0r = mn0; m1r = mn1;

        // ---- exp in-place; accumulate row sums ----
        float ls0 = 0.f, ls1 = 0.f;
#pragma unroll
        for (int nt = 0; nt < 16; nt++) {
            s[nt][0] = __expf(s[nt][0] - mn0);
            s[nt][1] = __expf(s[nt][1] - mn0);
            s[nt][2] = __expf(s[nt][2] - mn1);
            s[nt][3] = __expf(s[nt][3] - mn1);
            ls0 += s[nt][0] + s[nt][1];
            ls1 += s[nt][2] + s[nt][3];
        }
        l0 = l0 * fac0 + ls0;
        l1 = l1 * fac1 + ls1;
#pragma unroll
        for (int nt = 0; nt < 8; nt++) {
            o[nt][0] *= fac0; o[nt][1] *= fac0;
            o[nt][2] *= fac1; o[nt][3] *= fac1;
        }

        // ---- O += P V : P fragments converted in registers (no smem) ----
#pragma unroll
        for (int ks = 0; ks < 8; ks++) {
            unsigned ap[4];
            ap[0] = pack_h2(s[2 * ks][0], s[2 * ks][1]);
            ap[1] = pack_h2(s[2 * ks][2], s[2 * ks][3]);
            ap[2] = pack_h2(s[2 * ks + 1][0], s[2 * ks + 1][1]);
            ap[3] = pack_h2(s[2 * ks + 1][2], s[2 * ks + 1][3]);
#pragma unroll
            for (int nt = 0; nt < 8; nt++) {
                unsigned bv[2];
                bv[0] = Vu[(nt * 8 + g) * 68 + 8 * ks + t];
                bv[1] = Vu[(nt * 8 + g) * 68 + 8 * ks + t + 4];
                mma16(o[nt], ap, bv);
            }
        }
        __syncthreads();
    }

    // ---- finalize ----
    l0 += __shfl_xor_sync(0xffffffffu, l0, 1);
    l0 += __shfl_xor_sync(0xffffffffu, l0, 2);
    l1 += __shfl_xor_sync(0xffffffffu, l1, 1);
    l1 += __shfl_xor_sync(0xffffffffu, l1, 2);
    const float inv0 = 1.0f / l0, inv1 = 1.0f / l1;

    const int b = bh >> 4, h = bh & 15;
    __half* c0 = &g_ctx[(size_t)(b * LLEN + rowg) * DD + h * 64];
    __half* c1 = c0 + 8 * (size_t)DD;
#pragma unroll
    for (int nt = 0; nt < 8; nt++) {
        *(__half2*)&c0[nt * 8 + 2 * t] = __floats2half2_rn(o[nt][0] * inv0, o[nt][1] * inv0);
        *(__half2*)&c1[nt * 8 + 2 * t] = __floats2half2_rn(o[nt][2] * inv1, o[nt][3] * inv1);
    }
}

// ---------------- LayerNorm: grid 2048, 256 threads ----------------
__global__ __launch_bounds__(256)
void ln_kernel(const float* __restrict__ gamma, const float* __restrict__ beta,
               float* __restrict__ out)
{
    __shared__ float red[8];
    const int row = blockIdx.x, tid = threadIdx.x;
    const float4 xv = *(const float4*)&g_pre[(size_t)row * DD + tid * 4];

    float sv = xv.x + xv.y + xv.z + xv.w;
#pragma unroll
    for (int off = 16; off > 0; off >>= 1) sv += __shfl_xor_sync(0xffffffffu, sv, off);
    if ((tid & 31) == 0) red[tid >> 5] = sv;
    __syncthreads();
    float tot = 0.f;
#pragma unroll
    for (int w = 0; w < 8; w++) tot += red[w];
    const float mean = tot * (1.0f / 1024.0f);

    const float dx = xv.x - mean, dy = xv.y - mean, dz = xv.z - mean, dw = xv.w - mean;
    float ss = dx * dx + dy * dy + dz * dz + dw * dw;
    __syncthreads();
#pragma unroll
    for (int off = 16; off > 0; off >>= 1) ss += __shfl_xor_sync(0xffffffffu, ss, off);
    if ((tid & 31) == 0) red[tid >> 5] = ss;
    __syncthreads();
    float tot2 = 0.f;
#pragma unroll
    for (int w = 0; w < 8; w++) tot2 += red[w];
    const float rstd = rsqrtf(tot2 * (1.0f / 1024.0f) + 1e-6f);

    const float4 gv = *(const float4*)&gamma[tid * 4];
    const float4 bv = *(const float4*)&beta[tid * 4];
    float4 ov;
    ov.x = dx * rstd * gv.x + bv.x;
    ov.y = dy * rstd * gv.y + bv.y;
    ov.z = dz * rstd * gv.z + bv.z;
    ov.w = dw * rstd * gv.w + bv.w;
    *(float4*)&out[(size_t)row * DD + tid * 4] = ov;
}

// ---------------- launch ----------------
extern "C" void kernel_launch(void* const* d_in, const int* in_sizes, int n_in,
                              void* d_out, int out_size)
{
    const float* q     = (const float*)d_in[0];
    const float* k     = (const float*)d_in[1];
    const float* v     = (const float*)d_in[2];
    const float* bias  = (const float*)d_in[3];
    const float* gbias = (const float*)d_in[4];
    const float* wq    = (const float*)d_in[5];
    const float* bq    = (const float*)d_in[6];
    const float* wk    = (const float*)d_in[7];
    const float* bk    = (const float*)d_in[8];
    const float* wv    = (const float*)d_in[9];
    const float* bv    = (const float*)d_in[10];
    const float* wo    = (const float*)d_in[11];
    const float* bo    = (const float*)d_in[12];
    const float* ln_g  = (const float*)d_in[13];
    const float* ln_b  = (const float*)d_in[14];
    float* out = (float*)d_out;

    cudaFuncSetAttribute(gemm16,
                         cudaFuncAttributeMaxDynamicSharedMemorySize, GEMM_SMEM_BYTES);
    cudaFuncSetAttribute(attn_kernel,
                         cudaFuncAttributeMaxDynamicSharedMemorySize, ATTN_SMEM_BYTES);

    convert_in<<<MR * DD / 4 / 256, 256>>>(q, k, v);
    transpose_w<<<dim3(32, 32, 4), 256>>>(wq, wk, wv, wo);
    gemm16<<<dim3(8, 16, 3), 256, GEMM_SMEM_BYTES>>>(0, nullptr, bq, bk, bv);
    attn_kernel<<<dim3(4, 64), 256, ATTN_SMEM_BYTES>>>(bias, gbias);
    gemm16<<<dim3(8, 16, 1), 256, GEMM_SMEM_BYTES>>>(1, q, bo, nullptr, nullptr);
    ln_kernel<<<2048, 256>>>(ln_g, ln_b, out);
}